// round 1
// baseline (speedup 1.0000x reference)
#include <cuda_runtime.h>
#include <math.h>

// Problem constants
#define SQ   2048
#define NB   2
#define EMB  1024
#define NH   16
#define HD   64
#define MTOT (SQ * NB)          // 4096 rows (s,b)
#define SCALE 0.125f            // hd^-0.5

// Scratch (allocation-free rule: __device__ globals)
__device__ float g_q[(size_t)NB * NH * SQ * HD];
__device__ float g_k[(size_t)NB * NH * SQ * HD];
__device__ float g_v[(size_t)NB * NH * SQ * HD];
__device__ float g_ctx[(size_t)NB * NH * SQ * HD];

// ---------------------------------------------------------------------------
// Kernel 1: fused QKV projection.
//   qkv[m, n] = sum_k query[m, k] * W[n, k] + bias[n]
//   m = s*NB + b (query is (S,B,E) contiguous), n in [0, 3E)
//   Epilogue scatters into head-major g_q/g_k/g_v (B,H,S,hd); q pre-scaled.
// 64x64 tile, BK=16, 256 threads, 4x4 per thread.
// ---------------------------------------------------------------------------
__global__ __launch_bounds__(256)
void qkv_gemm(const float* __restrict__ A, const float* __restrict__ W,
              const float* __restrict__ bias)
{
    const int BM = 64, BN = 64, BK = 16;
    __shared__ float As[BK][BM + 4];   // +4 pad: keeps 16B alignment, kills store conflicts
    __shared__ float Bs[BK][BN + 4];

    int tid = threadIdx.x;
    int tx = tid & 15, ty = tid >> 4;
    int row0 = blockIdx.y * BM;
    int col0 = blockIdx.x * BN;

    float acc[4][4] = {};

    for (int k0 = 0; k0 < EMB; k0 += BK) {
        #pragma unroll
        for (int i = tid; i < BM * BK; i += 256) {
            int r = i >> 4, c = i & 15;
            As[c][r] = A[(size_t)(row0 + r) * EMB + k0 + c];
        }
        #pragma unroll
        for (int i = tid; i < BN * BK; i += 256) {
            int r = i >> 4, c = i & 15;
            Bs[c][r] = W[(size_t)(col0 + r) * EMB + k0 + c];
        }
        __syncthreads();

        #pragma unroll
        for (int kk = 0; kk < BK; kk++) {
            float4 a4 = *(const float4*)&As[kk][ty * 4];
            float4 b4 = *(const float4*)&Bs[kk][tx * 4];
            float a[4] = {a4.x, a4.y, a4.z, a4.w};
            float b[4] = {b4.x, b4.y, b4.z, b4.w};
            #pragma unroll
            for (int i = 0; i < 4; i++)
                #pragma unroll
                for (int j = 0; j < 4; j++)
                    acc[i][j] += a[i] * b[j];
        }
        __syncthreads();
    }

    #pragma unroll
    for (int i = 0; i < 4; i++) {
        int m = row0 + ty * 4 + i;
        int s = m / NB, b = m % NB;
        #pragma unroll
        for (int j = 0; j < 4; j++) {
            int n = col0 + tx * 4 + j;
            float val = acc[i][j] + bias[n];
            int sec = n / EMB;          // 0=q, 1=k, 2=v (uniform per block: 64 | 1024)
            int r   = n % EMB;
            int h = r >> 6, d = r & 63;
            size_t idx = ((size_t)(b * NH + h) * SQ + s) * HD + d;
            if (sec == 0)      g_q[idx] = val * SCALE;
            else if (sec == 1) g_k[idx] = val;
            else               g_v[idx] = val;
        }
    }
}

// ---------------------------------------------------------------------------
// Kernel 2: flash attention, fp32, online softmax.
// One thread = one query row. CTA = 128 query rows of one (b,h).
// K/V tiles of 32 rows staged in smem; q/o/s fully register-resident.
// ---------------------------------------------------------------------------
__global__ __launch_bounds__(128)
void flash()
{
    int bh   = blockIdx.y;                       // 0..31
    int qrow = blockIdx.x * 128 + threadIdx.x;   // 0..2047

    const float* qp = g_q + ((size_t)bh * SQ + qrow) * HD;
    const float* kp = g_k + (size_t)bh * SQ * HD;
    const float* vp = g_v + (size_t)bh * SQ * HD;

    __shared__ float Ks[32][HD];
    __shared__ float Vs[32][HD];
    float* ksf = &Ks[0][0];
    float* vsf = &Vs[0][0];

    float qr[HD];
    #pragma unroll
    for (int d = 0; d < HD; d++) qr[d] = qp[d];

    float o[HD];
    #pragma unroll
    for (int d = 0; d < HD; d++) o[d] = 0.f;
    float mmax = -1e30f, l = 0.f;

    for (int kt = 0; kt < SQ; kt += 32) {
        #pragma unroll
        for (int i = threadIdx.x; i < 32 * HD; i += 128) {
            ksf[i] = kp[(size_t)kt * HD + i];
            vsf[i] = vp[(size_t)kt * HD + i];
        }
        __syncthreads();

        float sarr[32];
        float tmax = mmax;
        #pragma unroll
        for (int j = 0; j < 32; j++) {
            float acc = 0.f;
            #pragma unroll
            for (int d = 0; d < HD; d++) acc += qr[d] * Ks[j][d];
            sarr[j] = acc;
            tmax = fmaxf(tmax, acc);
        }

        float corr = __expf(mmax - tmax);
        mmax = tmax;
        l *= corr;
        #pragma unroll
        for (int d = 0; d < HD; d++) o[d] *= corr;

        #pragma unroll
        for (int j = 0; j < 32; j++) {
            float p = __expf(sarr[j] - mmax);
            l += p;
            #pragma unroll
            for (int d = 0; d < HD; d++) o[d] += p * Vs[j][d];
        }
        __syncthreads();
    }

    float inv = 1.0f / l;
    float* op = g_ctx + ((size_t)bh * SQ + qrow) * HD;
    #pragma unroll
    for (int d = 0; d < HD; d++) op[d] = o[d] * inv;
}

// ---------------------------------------------------------------------------
// Kernel 3: output projection.
//   out[m, n] = sum_k ctx(m, k) * out_w[n, k] + out_b[n]
//   ctx(m, k) gathered from head-major g_ctx; out written (S,B,E) = m-major.
// ---------------------------------------------------------------------------
__global__ __launch_bounds__(256)
void out_gemm(const float* __restrict__ W, const float* __restrict__ bias,
              float* __restrict__ out)
{
    const int BM = 64, BN = 64, BK = 16;
    __shared__ float As[BK][BM + 4];
    __shared__ float Bs[BK][BN + 4];

    int tid = threadIdx.x;
    int tx = tid & 15, ty = tid >> 4;
    int row0 = blockIdx.y * BM;
    int col0 = blockIdx.x * BN;

    float acc[4][4] = {};

    for (int k0 = 0; k0 < EMB; k0 += BK) {
        #pragma unroll
        for (int i = tid; i < BM * BK; i += 256) {
            int r = i >> 4, c = i & 15;
            int m = row0 + r;
            int s = m / NB, b = m % NB;
            int kg = k0 + c;
            As[c][r] = g_ctx[((size_t)(b * NH + (kg >> 6)) * SQ + s) * HD + (kg & 63)];
        }
        #pragma unroll
        for (int i = tid; i < BN * BK; i += 256) {
            int r = i >> 4, c = i & 15;
            Bs[c][r] = W[(size_t)(col0 + r) * EMB + k0 + c];
        }
        __syncthreads();

        #pragma unroll
        for (int kk = 0; kk < BK; kk++) {
            float4 a4 = *(const float4*)&As[kk][ty * 4];
            float4 b4 = *(const float4*)&Bs[kk][tx * 4];
            float a[4] = {a4.x, a4.y, a4.z, a4.w};
            float b[4] = {b4.x, b4.y, b4.z, b4.w};
            #pragma unroll
            for (int i = 0; i < 4; i++)
                #pragma unroll
                for (int j = 0; j < 4; j++)
                    acc[i][j] += a[i] * b[j];
        }
        __syncthreads();
    }

    #pragma unroll
    for (int i = 0; i < 4; i++) {
        int m = row0 + ty * 4 + i;
        #pragma unroll
        for (int j = 0; j < 4; j++) {
            int n = col0 + tx * 4 + j;
            out[(size_t)m * EMB + n] = acc[i][j] + bias[n];
        }
    }
}

// ---------------------------------------------------------------------------
extern "C" void kernel_launch(void* const* d_in, const int* in_sizes, int n_in,
                              void* d_out, int out_size)
{
    const float* query = (const float*)d_in[0];   // (S,B,E)
    const float* w_in  = (const float*)d_in[1];   // (3E,E)
    const float* b_in  = (const float*)d_in[2];   // (3E,)
    const float* w_out = (const float*)d_in[3];   // (E,E)
    const float* b_out = (const float*)d_in[4];   // (E,)
    float* out = (float*)d_out;                   // (S,B,E)

    // 1) QKV projection: M=4096, N=3072, K=1024
    qkv_gemm<<<dim3(3 * EMB / 64, MTOT / 64), 256>>>(query, w_in, b_in);
    // 2) Attention: grid (q-tiles, B*H)
    flash<<<dim3(SQ / 128, NB * NH), 128>>>();
    // 3) Output projection: M=4096, N=1024, K=1024
    out_gemm<<<dim3(EMB / 64, MTOT / 64), 256>>>(w_out, b_out, out);
}

// round 5
// speedup vs baseline: 5.9644x; 5.9644x over previous
#include <cuda_runtime.h>
#include <cuda_fp16.h>
#include <math.h>

// Problem constants
#define SQ   2048
#define NB   2
#define EMB  1024
#define NH   16
#define HD   64
#define MTOT (SQ * NB)          // 4096
#define SCALE 0.125f

// ---------------- fp16 scratch (allocation-free: __device__ globals) -------
__device__ __half g_xh [(size_t)MTOT * EMB];       // query fp16, m-major
__device__ __half g_w1h[(size_t)3 * EMB * EMB];    // in_proj_weight fp16
__device__ __half g_w2h[(size_t)EMB * EMB];        // out_w fp16
__device__ __half g_qh [(size_t)NB * NH * SQ * HD]; // (b,h,s,d), pre-scaled
__device__ __half g_kh [(size_t)NB * NH * SQ * HD]; // (b,h,s,d)
__device__ __half g_vth[(size_t)NB * NH * HD * SQ]; // (b,h,d,s)  TRANSPOSED
__device__ __half g_ctxh[(size_t)NB * NH * SQ * HD];// (b,h,s,d)

// ---------------- helpers --------------------------------------------------
__device__ __forceinline__ unsigned smem_u32p(const void* p) {
    return (unsigned)__cvta_generic_to_shared(p);
}
__device__ __forceinline__ void cpa8(unsigned dst, const void* src) {
    asm volatile("cp.async.ca.shared.global [%0], [%1], 8;\n" :: "r"(dst), "l"(src));
}
__device__ __forceinline__ void cp_commit() { asm volatile("cp.async.commit_group;\n"); }
__device__ __forceinline__ void cp_wait0()  { asm volatile("cp.async.wait_group 0;\n" ::: "memory"); }

__device__ __forceinline__ void mma16816(float* c, const unsigned* a, const unsigned* b) {
    asm volatile(
        "mma.sync.aligned.m16n8k16.row.col.f32.f16.f16.f32 "
        "{%0,%1,%2,%3},{%4,%5,%6,%7},{%8,%9},{%0,%1,%2,%3};\n"
        : "+f"(c[0]), "+f"(c[1]), "+f"(c[2]), "+f"(c[3])
        : "r"(a[0]), "r"(a[1]), "r"(a[2]), "r"(a[3]), "r"(b[0]), "r"(b[1]));
}

// ---------------- fp32 -> fp16 convert (vectorized) ------------------------
__global__ void convert_f2h4(const float4* __restrict__ src, int n4, int which) {
    __half2* dst = (which == 0) ? (__half2*)g_xh
                 : (which == 1) ? (__half2*)g_w1h
                                : (__half2*)g_w2h;
    int i = blockIdx.x * blockDim.x + threadIdx.x;
    if (i < n4) {
        float4 v = src[i];
        dst[2 * i]     = __floats2half2_rn(v.x, v.y);
        dst[2 * i + 1] = __floats2half2_rn(v.z, v.w);
    }
}

// ---------------- GEMM: C[m,n] = sum_k A[m,k] * W[n,k] ---------------------
// 128x128x32 tile, 8 warps (4x2), warp tile 32x64, mma m16n8k16.
// MODE 0: A = g_xh, W = g_w1h, epilogue scatters q/k/v (v transposed).
// MODE 1: A = g_ctxh (gathered), W = g_w2h, epilogue writes fp32 out + bias.
#define BM 128
#define BN 128
#define BKG 32
#define GST 36      // smem row stride in halves (pad vs 32)

template<int MODE>
__global__ __launch_bounds__(256)
void gemm_h(const float* __restrict__ bias, float* __restrict__ outp)
{
    __shared__ __align__(16) __half As[2][BM * GST];
    __shared__ __align__(16) __half Ws[2][BN * GST];

    const __half* A = (MODE == 0) ? g_xh  : g_ctxh;
    const __half* W = (MODE == 0) ? g_w1h : g_w2h;

    int tid  = threadIdx.x;
    int bm   = blockIdx.y, bn = blockIdx.x;
    int warp = tid >> 5, lane = tid & 31;
    int wm = warp & 3, wn = warp >> 2;
    int g = lane >> 2, tig = lane & 3;

    float c[2][8][4];
    #pragma unroll
    for (int mt = 0; mt < 2; mt++)
        #pragma unroll
        for (int nt = 0; nt < 8; nt++)
            #pragma unroll
            for (int i = 0; i < 4; i++) c[mt][nt][i] = 0.f;

    auto stage = [&](int buf, int k0) {
        #pragma unroll
        for (int j = 0; j < 4; j++) {
            int i = tid + j * 256;
            int row = i >> 3, ch = i & 7;
            const __half* src;
            if (MODE == 0) {
                src = A + (size_t)(bm * BM + row) * EMB + k0 + ch * 4;
            } else {
                int m = bm * BM + row;
                int s = m >> 1, b = m & 1;
                int kg = k0 + ch * 4;
                src = A + (((size_t)(b * NH + (kg >> 6)) * SQ + s) * HD + (kg & 63));
            }
            cpa8(smem_u32p(&As[buf][row * GST + ch * 4]), src);
        }
        #pragma unroll
        for (int j = 0; j < 4; j++) {
            int i = tid + j * 256;
            int row = i >> 3, ch = i & 7;
            cpa8(smem_u32p(&Ws[buf][row * GST + ch * 4]),
                 W + (size_t)(bn * BN + row) * EMB + k0 + ch * 4);
        }
        cp_commit();
    };

    stage(0, 0);
    const int NKT = EMB / BKG;   // 32
    for (int t = 0; t < NKT; t++) {
        cp_wait0();
        __syncthreads();
        if (t + 1 < NKT) stage((t + 1) & 1, (t + 1) * BKG);
        int buf = t & 1;

        #pragma unroll
        for (int ks = 0; ks < 2; ks++) {
            unsigned afr[2][4], bfr[8][2];
            #pragma unroll
            for (int mt = 0; mt < 2; mt++) {
                const __half* b0 = &As[buf][(wm * 32 + mt * 16 + g) * GST + ks * 16 + 2 * tig];
                afr[mt][0] = *(const unsigned*)(b0);
                afr[mt][1] = *(const unsigned*)(b0 + 8 * GST);
                afr[mt][2] = *(const unsigned*)(b0 + 8);
                afr[mt][3] = *(const unsigned*)(b0 + 8 * GST + 8);
            }
            #pragma unroll
            for (int nt = 0; nt < 8; nt++) {
                const __half* wb = &Ws[buf][(wn * 64 + nt * 8 + g) * GST + ks * 16 + 2 * tig];
                bfr[nt][0] = *(const unsigned*)(wb);
                bfr[nt][1] = *(const unsigned*)(wb + 8);
            }
            #pragma unroll
            for (int mt = 0; mt < 2; mt++)
                #pragma unroll
                for (int nt = 0; nt < 8; nt++)
                    mma16816(c[mt][nt], afr[mt], bfr[nt]);
        }
    }

    // epilogue
    #pragma unroll
    for (int mt = 0; mt < 2; mt++) {
        #pragma unroll
        for (int nt = 0; nt < 8; nt++) {
            #pragma unroll
            for (int i = 0; i < 4; i++) {
                int row = bm * BM + wm * 32 + mt * 16 + g + ((i >= 2) ? 8 : 0);
                int col = bn * BN + wn * 64 + nt * 8 + 2 * tig + (i & 1);
                float val = c[mt][nt][i] + bias[col];
                if (MODE == 0) {
                    int sec = col >> 10;          // 0=q 1=k 2=v
                    int r = col & 1023;
                    int h = r >> 6, d = r & 63;
                    int s = row >> 1, b = row & 1;
                    if (sec == 0)
                        g_qh[((size_t)(b * NH + h) * SQ + s) * HD + d] = __float2half(val * SCALE);
                    else if (sec == 1)
                        g_kh[((size_t)(b * NH + h) * SQ + s) * HD + d] = __float2half(val);
                    else
                        g_vth[((size_t)(b * NH + h) * HD + d) * SQ + s] = __float2half(val);
                } else {
                    outp[(size_t)row * EMB + col] = val;
                }
            }
        }
    }
}

// ---------------- Flash attention, fp16 HMMA, online softmax ---------------
// CTA: 64 query rows of one (b,h); 4 warps x 16 rows. K/V tiles of 64.
#define KST 72      // smem row stride in halves (64 + 8 pad; 144B = 16B-multiple)

__global__ __launch_bounds__(128)
void flash_h()
{
    __shared__ __align__(16) __half Qs[64 * KST];
    __shared__ __align__(16) __half Ks[64 * KST];
    __shared__ __align__(16) __half Vt[64 * KST];   // [hd][key]

    int bh = blockIdx.y;
    int q0 = blockIdx.x * 64;
    int tid = threadIdx.x, warp = tid >> 5, lane = tid & 31;
    int g = lane >> 2, tig = lane & 3;

    const __half* qbase = g_qh + ((size_t)bh * SQ + q0) * HD;
    const __half* kbase = g_kh + (size_t)bh * SQ * HD;
    const __half* vbase = g_vth + (size_t)bh * HD * SQ;

    // stage Q tile (64x64)
    #pragma unroll
    for (int j = 0; j < 4; j++) {
        int i = tid + j * 128;
        int r = i >> 3, ch = i & 7;
        *(uint4*)&Qs[r * KST + ch * 8] = *(const uint4*)(qbase + (size_t)r * HD + ch * 8);
    }
    __syncthreads();

    // Q fragments: 4 k-steps of m16k16 per warp
    unsigned qf[4][4];
    #pragma unroll
    for (int ks = 0; ks < 4; ks++) {
        const __half* b0 = &Qs[(warp * 16 + g) * KST + ks * 16 + 2 * tig];
        qf[ks][0] = *(const unsigned*)(b0);
        qf[ks][1] = *(const unsigned*)(b0 + 8 * KST);
        qf[ks][2] = *(const unsigned*)(b0 + 8);
        qf[ks][3] = *(const unsigned*)(b0 + 8 * KST + 8);
    }

    float o[8][4];
    #pragma unroll
    for (int nt = 0; nt < 8; nt++)
        #pragma unroll
        for (int i = 0; i < 4; i++) o[nt][i] = 0.f;
    float m0 = -1e30f, m1 = -1e30f, l0 = 0.f, l1 = 0.f;

    for (int kt = 0; kt < SQ; kt += 64) {
        __syncthreads();   // previous-iteration readers done before restage
        #pragma unroll
        for (int j = 0; j < 4; j++) {
            int i = tid + j * 128;
            int r = i >> 3, ch = i & 7;
            *(uint4*)&Ks[r * KST + ch * 8] = *(const uint4*)(kbase + (size_t)(kt + r) * HD + ch * 8);
            *(uint4*)&Vt[r * KST + ch * 8] = *(const uint4*)(vbase + (size_t)r * SQ + kt + ch * 8);
        }
        __syncthreads();

        // S = Q K^T  (16 x 64 per warp)
        float s[8][4];
        #pragma unroll
        for (int nt = 0; nt < 8; nt++)
            #pragma unroll
            for (int i = 0; i < 4; i++) s[nt][i] = 0.f;
        #pragma unroll
        for (int ks = 0; ks < 4; ks++) {
            #pragma unroll
            for (int nt = 0; nt < 8; nt++) {
                unsigned bf[2];
                const __half* kb = &Ks[(nt * 8 + g) * KST + ks * 16 + 2 * tig];
                bf[0] = *(const unsigned*)(kb);
                bf[1] = *(const unsigned*)(kb + 8);
                mma16816(s[nt], qf[ks], bf);
            }
        }

        // rowwise max (rows g -> m0, g+8 -> m1)
        float t0 = -1e30f, t1 = -1e30f;
        #pragma unroll
        for (int nt = 0; nt < 8; nt++) {
            t0 = fmaxf(t0, fmaxf(s[nt][0], s[nt][1]));
            t1 = fmaxf(t1, fmaxf(s[nt][2], s[nt][3]));
        }
        t0 = fmaxf(t0, __shfl_xor_sync(0xffffffffu, t0, 1));
        t0 = fmaxf(t0, __shfl_xor_sync(0xffffffffu, t0, 2));
        t1 = fmaxf(t1, __shfl_xor_sync(0xffffffffu, t1, 1));
        t1 = fmaxf(t1, __shfl_xor_sync(0xffffffffu, t1, 2));

        float nm0 = fmaxf(m0, t0), nm1 = fmaxf(m1, t1);
        float sc0 = __expf(m0 - nm0), sc1 = __expf(m1 - nm1);
        m0 = nm0; m1 = nm1;
        l0 *= sc0; l1 *= sc1;
        #pragma unroll
        for (int nt = 0; nt < 8; nt++) {
            o[nt][0] *= sc0; o[nt][1] *= sc0;
            o[nt][2] *= sc1; o[nt][3] *= sc1;
        }

        // P = exp(S - m); pack to fp16 A-fragments; accumulate l from ROUNDED P
        unsigned pf[4][4];
        float ps0 = 0.f, ps1 = 0.f;
        #pragma unroll
        for (int ks = 0; ks < 4; ks++) {
            int ta = 2 * ks, tb = 2 * ks + 1;
            __half2 h0 = __floats2half2_rn(__expf(s[ta][0] - m0), __expf(s[ta][1] - m0));
            __half2 h1 = __floats2half2_rn(__expf(s[ta][2] - m1), __expf(s[ta][3] - m1));
            __half2 h2 = __floats2half2_rn(__expf(s[tb][0] - m0), __expf(s[tb][1] - m0));
            __half2 h3 = __floats2half2_rn(__expf(s[tb][2] - m1), __expf(s[tb][3] - m1));
            pf[ks][0] = *(unsigned*)&h0;
            pf[ks][1] = *(unsigned*)&h1;
            pf[ks][2] = *(unsigned*)&h2;
            pf[ks][3] = *(unsigned*)&h3;
            float2 f;
            f = __half22float2(h0); ps0 += f.x + f.y;
            f = __half22float2(h2); ps0 += f.x + f.y;
            f = __half22float2(h1); ps1 += f.x + f.y;
            f = __half22float2(h3); ps1 += f.x + f.y;
        }
        ps0 += __shfl_xor_sync(0xffffffffu, ps0, 1);
        ps0 += __shfl_xor_sync(0xffffffffu, ps0, 2);
        ps1 += __shfl_xor_sync(0xffffffffu, ps1, 1);
        ps1 += __shfl_xor_sync(0xffffffffu, ps1, 2);
        l0 += ps0; l1 += ps1;

        // O += P V   (B fragments from transposed V tile: contiguous pairs)
        #pragma unroll
        for (int ks = 0; ks < 4; ks++) {
            #pragma unroll
            for (int nt = 0; nt < 8; nt++) {
                unsigned bf[2];
                const __half* vb = &Vt[(nt * 8 + g) * KST + ks * 16 + 2 * tig];
                bf[0] = *(const unsigned*)(vb);
                bf[1] = *(const unsigned*)(vb + 8);
                mma16816(o[nt], pf[ks], bf);
            }
        }
    }

    // normalize + write ctx (fp16)
    float inv0 = 1.f / l0, inv1 = 1.f / l1;
    int row0 = q0 + warp * 16 + g;
    __half* obase = g_ctxh + (size_t)bh * SQ * HD;
    #pragma unroll
    for (int nt = 0; nt < 8; nt++) {
        int colb = nt * 8 + 2 * tig;
        __half2 ha = __floats2half2_rn(o[nt][0] * inv0, o[nt][1] * inv0);
        __half2 hb = __floats2half2_rn(o[nt][2] * inv1, o[nt][3] * inv1);
        *(__half2*)&obase[(size_t)row0 * HD + colb] = ha;
        *(__half2*)&obase[(size_t)(row0 + 8) * HD + colb] = hb;
    }
}

// ---------------------------------------------------------------------------
extern "C" void kernel_launch(void* const* d_in, const int* in_sizes, int n_in,
                              void* d_out, int out_size)
{
    const float* query = (const float*)d_in[0];   // (S,B,E)
    const float* w_in  = (const float*)d_in[1];   // (3E,E)
    const float* b_in  = (const float*)d_in[2];   // (3E,)
    const float* w_out = (const float*)d_in[3];   // (E,E)
    const float* b_out = (const float*)d_in[4];   // (E,)
    float* out = (float*)d_out;                   // (S,B,E)

    int n0 = MTOT * EMB / 4, n1 = 3 * EMB * EMB / 4, n2 = EMB * EMB / 4;
    convert_f2h4<<<(n0 + 255) / 256, 256>>>((const float4*)query, n0, 0);
    convert_f2h4<<<(n1 + 255) / 256, 256>>>((const float4*)w_in,  n1, 1);
    convert_f2h4<<<(n2 + 255) / 256, 256>>>((const float4*)w_out, n2, 2);

    // QKV: M=4096, N=3072, K=1024
    gemm_h<0><<<dim3(3 * EMB / BN, MTOT / BM), 256>>>(b_in, nullptr);
    // Attention
    flash_h<<<dim3(SQ / 64, NB * NH), 128>>>();
    // Out proj: M=4096, N=1024, K=1024
    gemm_h<1><<<dim3(EMB / BN, MTOT / BM), 256>>>(b_out, out);
}

// round 6
// speedup vs baseline: 8.0940x; 1.3570x over previous
#include <cuda_runtime.h>
#include <cuda_fp16.h>
#include <math.h>

// Problem constants
#define SQ   2048
#define NB   2
#define EMB  1024
#define NH   16
#define HD   64
#define MTOT (SQ * NB)          // 4096
#define SCALE 0.125f

// ---------------- fp16 scratch (allocation-free: __device__ globals) -------
__device__ __half g_xh [(size_t)MTOT * EMB];        // query fp16, m-major
__device__ __half g_w1h[(size_t)3 * EMB * EMB];     // in_proj_weight fp16
__device__ __half g_w2h[(size_t)EMB * EMB];         // out_w fp16
__device__ __half g_qh [(size_t)NB * NH * SQ * HD]; // (b,h,s,d), pre-scaled
__device__ __half g_kh [(size_t)NB * NH * SQ * HD]; // (b,h,s,d)
__device__ __half g_vth[(size_t)NB * NH * HD * SQ]; // (b,h,d,s)  TRANSPOSED
__device__ __half g_ctxh[(size_t)NB * NH * SQ * HD];// (b,h,s,d)

// ---------------- helpers --------------------------------------------------
__device__ __forceinline__ unsigned smem_u32p(const void* p) {
    return (unsigned)__cvta_generic_to_shared(p);
}
__device__ __forceinline__ void cpa16(unsigned dst, const void* src) {
    asm volatile("cp.async.cg.shared.global [%0], [%1], 16;\n" :: "r"(dst), "l"(src));
}
__device__ __forceinline__ void cp_commit() { asm volatile("cp.async.commit_group;\n"); }
__device__ __forceinline__ void cp_wait0()  { asm volatile("cp.async.wait_group 0;\n" ::: "memory"); }

__device__ __forceinline__ void mma16816(float* c, const unsigned* a, const unsigned* b) {
    asm volatile(
        "mma.sync.aligned.m16n8k16.row.col.f32.f16.f16.f32 "
        "{%0,%1,%2,%3},{%4,%5,%6,%7},{%8,%9},{%0,%1,%2,%3};\n"
        : "+f"(c[0]), "+f"(c[1]), "+f"(c[2]), "+f"(c[3])
        : "r"(a[0]), "r"(a[1]), "r"(a[2]), "r"(a[3]), "r"(b[0]), "r"(b[1]));
}
__device__ __forceinline__ void ldsmx4(unsigned* r, const __half* p) {
    unsigned addr = smem_u32p(p);
    asm volatile("ldmatrix.sync.aligned.m8n8.x4.shared.b16 {%0,%1,%2,%3}, [%4];\n"
        : "=r"(r[0]), "=r"(r[1]), "=r"(r[2]), "=r"(r[3]) : "r"(addr));
}

// ---------------- fp32 -> fp16 convert (vectorized) ------------------------
__global__ void convert_f2h4(const float4* __restrict__ src, int n4, int which) {
    __half2* dst = (which == 0) ? (__half2*)g_xh
                 : (which == 1) ? (__half2*)g_w1h
                                : (__half2*)g_w2h;
    int i = blockIdx.x * blockDim.x + threadIdx.x;
    if (i < n4) {
        float4 v = src[i];
        dst[2 * i]     = __floats2half2_rn(v.x, v.y);
        dst[2 * i + 1] = __floats2half2_rn(v.z, v.w);
    }
}

// ---------------- GEMM: C[m,n] = sum_k A[m,k] * W[n,k] ---------------------
// 128x128x32 tile, 8 warps (4x2), warp tile 32x64, mma m16n8k16.
// Swizzled smem (rows of 32 halves = 64B, chunk^((row>>1)&3)), ldmatrix frags.
#define BM 128
#define BN 128
#define BK 32

template<int MODE>
__global__ __launch_bounds__(256, 2)
void gemm_h(const float* __restrict__ bias, float* __restrict__ outp)
{
    __shared__ __align__(16) __half As[2][BM * BK];   // 8 KB each
    __shared__ __align__(16) __half Ws[2][BN * BK];

    const __half* A = (MODE == 0) ? g_xh  : g_ctxh;
    const __half* W = (MODE == 0) ? g_w1h : g_w2h;

    int tid  = threadIdx.x;
    int bm   = blockIdx.y, bn = blockIdx.x;
    int warp = tid >> 5, lane = tid & 31;
    int wm = warp & 3, wn = warp >> 2;

    float c[2][8][4];
    #pragma unroll
    for (int mt = 0; mt < 2; mt++)
        #pragma unroll
        for (int nt = 0; nt < 8; nt++)
            #pragma unroll
            for (int i = 0; i < 4; i++) c[mt][nt][i] = 0.f;

    auto stage = [&](int buf, int k0) {
        #pragma unroll
        for (int j = 0; j < 2; j++) {
            int i = tid + j * 256;          // 0..511
            int row = i >> 2, cc = i & 3;   // chunk = 8 halves = 16B
            const __half* src;
            if (MODE == 0) {
                src = A + (size_t)(bm * BM + row) * EMB + k0 + cc * 8;
            } else {
                int m = bm * BM + row;
                int s = m >> 1, b = m & 1;
                int kg = k0 + cc * 8;
                src = A + (((size_t)(b * NH + (kg >> 6)) * SQ + s) * HD + (kg & 63));
            }
            int pc = cc ^ ((row >> 1) & 3);
            cpa16(smem_u32p(&As[buf][row * BK + pc * 8]), src);
        }
        #pragma unroll
        for (int j = 0; j < 2; j++) {
            int i = tid + j * 256;
            int row = i >> 2, cc = i & 3;
            int pc = cc ^ ((row >> 1) & 3);
            cpa16(smem_u32p(&Ws[buf][row * BK + pc * 8]),
                  W + (size_t)(bn * BN + row) * EMB + k0 + cc * 8);
        }
        cp_commit();
    };

    stage(0, 0);
    const int NKT = EMB / BK;   // 32
    for (int t = 0; t < NKT; t++) {
        cp_wait0();
        __syncthreads();
        if (t + 1 < NKT) stage((t + 1) & 1, (t + 1) * BK);
        int buf = t & 1;

        #pragma unroll
        for (int ks = 0; ks < 2; ks++) {
            unsigned afr[2][4], bfr[8][2];
            int cc = 2 * ks + (lane >> 4);
            #pragma unroll
            for (int mt = 0; mt < 2; mt++) {
                int r = wm * 32 + mt * 16 + (lane & 15);
                int pc = cc ^ ((r >> 1) & 3);
                ldsmx4(afr[mt], &As[buf][r * BK + pc * 8]);
            }
            #pragma unroll
            for (int np = 0; np < 4; np++) {
                int n = wn * 64 + np * 16 + (lane & 15);
                int pc = cc ^ ((n >> 1) & 3);
                unsigned rr[4];
                ldsmx4(rr, &Ws[buf][n * BK + pc * 8]);
                bfr[2 * np][0]     = rr[0]; bfr[2 * np][1]     = rr[2];
                bfr[2 * np + 1][0] = rr[1]; bfr[2 * np + 1][1] = rr[3];
            }
            #pragma unroll
            for (int mt = 0; mt < 2; mt++)
                #pragma unroll
                for (int nt = 0; nt < 8; nt++)
                    mma16816(c[mt][nt], afr[mt], bfr[nt]);
        }
    }

    // epilogue
    int g = lane >> 2, tig = lane & 3;
    #pragma unroll
    for (int mt = 0; mt < 2; mt++) {
        #pragma unroll
        for (int nt = 0; nt < 8; nt++) {
            #pragma unroll
            for (int i = 0; i < 4; i++) {
                int row = bm * BM + wm * 32 + mt * 16 + g + ((i >= 2) ? 8 : 0);
                int col = bn * BN + wn * 64 + nt * 8 + 2 * tig + (i & 1);
                float val = c[mt][nt][i] + bias[col];
                if (MODE == 0) {
                    int sec = col >> 10;          // 0=q 1=k 2=v
                    int r = col & 1023;
                    int h = r >> 6, d = r & 63;
                    int s = row >> 1, b = row & 1;
                    if (sec == 0)
                        g_qh[((size_t)(b * NH + h) * SQ + s) * HD + d] = __float2half(val * SCALE);
                    else if (sec == 1)
                        g_kh[((size_t)(b * NH + h) * SQ + s) * HD + d] = __float2half(val);
                    else
                        g_vth[((size_t)(b * NH + h) * HD + d) * SQ + s] = __float2half(val);
                } else {
                    outp[(size_t)row * EMB + col] = val;
                }
            }
        }
    }
}

// ---------------- Flash attention, fp16 HMMA, online softmax ---------------
// CTA: 64 query rows of one (b,h); 4 warps x 16 rows. K/V tiles of 64,
// double-buffered cp.async, swizzled 128B rows, ldmatrix fragments.
__global__ __launch_bounds__(128, 4)
void flash_h()
{
    __shared__ __align__(16) __half Qs[64 * HD];       // 8 KB
    __shared__ __align__(16) __half Ks[2][64 * HD];    // 16 KB
    __shared__ __align__(16) __half Vt[2][64 * HD];    // 16 KB  [hd][key]

    int bh = blockIdx.y;
    int q0 = blockIdx.x * 64;
    int tid = threadIdx.x, warp = tid >> 5, lane = tid & 31;
    int g = lane >> 2, tig = lane & 3;

    const __half* qbase = g_qh + ((size_t)bh * SQ + q0) * HD;
    const __half* kbase = g_kh + (size_t)bh * SQ * HD;
    const __half* vbase = g_vth + (size_t)bh * HD * SQ;

    auto stageKV = [&](int buf, int kt) {
        #pragma unroll
        for (int j = 0; j < 4; j++) {
            int i = tid + j * 128;          // 0..511
            int r = i >> 3, cc = i & 7;     // 8 chunks of 16B per 128B row
            int pc = cc ^ (r & 7);
            cpa16(smem_u32p(&Ks[buf][r * HD + pc * 8]),
                  kbase + (size_t)(kt + r) * HD + cc * 8);
            cpa16(smem_u32p(&Vt[buf][r * HD + pc * 8]),
                  vbase + (size_t)r * SQ + kt + cc * 8);
        }
        cp_commit();
    };

    // stage Q + first K/V tile
    #pragma unroll
    for (int j = 0; j < 4; j++) {
        int i = tid + j * 128;
        int r = i >> 3, cc = i & 7;
        int pc = cc ^ (r & 7);
        cpa16(smem_u32p(&Qs[r * HD + pc * 8]), qbase + (size_t)r * HD + cc * 8);
    }
    stageKV(0, 0);
    cp_wait0();
    __syncthreads();

    // Q fragments: 4 k-steps of m16k16 per warp (ldmatrix)
    unsigned qf[4][4];
    #pragma unroll
    for (int ks = 0; ks < 4; ks++) {
        int r = warp * 16 + (lane & 15);
        int cc = 2 * ks + (lane >> 4);
        int pc = cc ^ (r & 7);
        ldsmx4(qf[ks], &Qs[r * HD + pc * 8]);
    }

    float o[8][4];
    #pragma unroll
    for (int nt = 0; nt < 8; nt++)
        #pragma unroll
        for (int i = 0; i < 4; i++) o[nt][i] = 0.f;
    float m0 = -1e30f, m1 = -1e30f, l0 = 0.f, l1 = 0.f;

    const int NT = SQ / 64;   // 32
    for (int it = 0; it < NT; it++) {
        if (it > 0) {
            cp_wait0();        // tile it arrived
            __syncthreads();   // all warps done reading buf^1 (tile it-1)
        }
        if (it + 1 < NT) stageKV((it + 1) & 1, (it + 1) * 64);
        int buf = it & 1;

        // S = Q K^T  (16 x 64 per warp)
        float s[8][4];
        #pragma unroll
        for (int nt = 0; nt < 8; nt++)
            #pragma unroll
            for (int i = 0; i < 4; i++) s[nt][i] = 0.f;
        #pragma unroll
        for (int ks = 0; ks < 4; ks++) {
            int cc = 2 * ks + (lane >> 4);
            #pragma unroll
            for (int np = 0; np < 4; np++) {
                int n = np * 16 + (lane & 15);
                int pc = cc ^ (n & 7);
                unsigned rr[4];
                ldsmx4(rr, &Ks[buf][n * HD + pc * 8]);
                unsigned bA[2] = {rr[0], rr[2]};
                unsigned bB[2] = {rr[1], rr[3]};
                mma16816(s[2 * np],     qf[ks], bA);
                mma16816(s[2 * np + 1], qf[ks], bB);
            }
        }

        // rowwise max (rows g -> m0, g+8 -> m1)
        float t0 = -1e30f, t1 = -1e30f;
        #pragma unroll
        for (int nt = 0; nt < 8; nt++) {
            t0 = fmaxf(t0, fmaxf(s[nt][0], s[nt][1]));
            t1 = fmaxf(t1, fmaxf(s[nt][2], s[nt][3]));
        }
        t0 = fmaxf(t0, __shfl_xor_sync(0xffffffffu, t0, 1));
        t0 = fmaxf(t0, __shfl_xor_sync(0xffffffffu, t0, 2));
        t1 = fmaxf(t1, __shfl_xor_sync(0xffffffffu, t1, 1));
        t1 = fmaxf(t1, __shfl_xor_sync(0xffffffffu, t1, 2));

        float nm0 = fmaxf(m0, t0), nm1 = fmaxf(m1, t1);
        float sc0 = __expf(m0 - nm0), sc1 = __expf(m1 - nm1);
        m0 = nm0; m1 = nm1;
        l0 *= sc0; l1 *= sc1;
        #pragma unroll
        for (int nt = 0; nt < 8; nt++) {
            o[nt][0] *= sc0; o[nt][1] *= sc0;
            o[nt][2] *= sc1; o[nt][3] *= sc1;
        }

        // P = exp(S - m); pack to fp16 A-fragments; accumulate l from ROUNDED P
        unsigned pf[4][4];
        float ps0 = 0.f, ps1 = 0.f;
        #pragma unroll
        for (int ks = 0; ks < 4; ks++) {
            int ta = 2 * ks, tb = 2 * ks + 1;
            __half2 h0 = __floats2half2_rn(__expf(s[ta][0] - m0), __expf(s[ta][1] - m0));
            __half2 h1 = __floats2half2_rn(__expf(s[ta][2] - m1), __expf(s[ta][3] - m1));
            __half2 h2 = __floats2half2_rn(__expf(s[tb][0] - m0), __expf(s[tb][1] - m0));
            __half2 h3 = __floats2half2_rn(__expf(s[tb][2] - m1), __expf(s[tb][3] - m1));
            pf[ks][0] = *(unsigned*)&h0;
            pf[ks][1] = *(unsigned*)&h1;
            pf[ks][2] = *(unsigned*)&h2;
            pf[ks][3] = *(unsigned*)&h3;
            float2 f;
            f = __half22float2(h0); ps0 += f.x + f.y;
            f = __half22float2(h2); ps0 += f.x + f.y;
            f = __half22float2(h1); ps1 += f.x + f.y;
            f = __half22float2(h3); ps1 += f.x + f.y;
        }
        ps0 += __shfl_xor_sync(0xffffffffu, ps0, 1);
        ps0 += __shfl_xor_sync(0xffffffffu, ps0, 2);
        ps1 += __shfl_xor_sync(0xffffffffu, ps1, 1);
        ps1 += __shfl_xor_sync(0xffffffffu, ps1, 2);
        l0 += ps0; l1 += ps1;

        // O += P V   (B fragments from transposed V tile via ldmatrix)
        #pragma unroll
        for (int ks = 0; ks < 4; ks++) {
            int cc = 2 * ks + (lane >> 4);      // key-chunk
            #pragma unroll
            for (int np = 0; np < 4; np++) {
                int r = np * 16 + (lane & 15);  // d-dim row
                int pc = cc ^ (r & 7);
                unsigned rr[4];
                ldsmx4(rr, &Vt[buf][r * HD + pc * 8]);
                unsigned bA[2] = {rr[0], rr[2]};
                unsigned bB[2] = {rr[1], rr[3]};
                mma16816(o[2 * np],     pf[ks], bA);
                mma16816(o[2 * np + 1], pf[ks], bB);
            }
        }
    }

    // normalize + write ctx (fp16)
    float inv0 = 1.f / l0, inv1 = 1.f / l1;
    int row0 = q0 + warp * 16 + g;
    __half* obase = g_ctxh + (size_t)bh * SQ * HD;
    #pragma unroll
    for (int nt = 0; nt < 8; nt++) {
        int colb = nt * 8 + 2 * tig;
        __half2 ha = __floats2half2_rn(o[nt][0] * inv0, o[nt][1] * inv0);
        __half2 hb = __floats2half2_rn(o[nt][2] * inv1, o[nt][3] * inv1);
        *(__half2*)&obase[(size_t)row0 * HD + colb] = ha;
        *(__half2*)&obase[(size_t)(row0 + 8) * HD + colb] = hb;
    }
}

// ---------------------------------------------------------------------------
extern "C" void kernel_launch(void* const* d_in, const int* in_sizes, int n_in,
                              void* d_out, int out_size)
{
    const float* query = (const float*)d_in[0];   // (S,B,E)
    const float* w_in  = (const float*)d_in[1];   // (3E,E)
    const float* b_in  = (const float*)d_in[2];   // (3E,)
    const float* w_out = (const float*)d_in[3];   // (E,E)
    const float* b_out = (const float*)d_in[4];   // (E,)
    float* out = (float*)d_out;                   // (S,B,E)

    int n0 = MTOT * EMB / 4, n1 = 3 * EMB * EMB / 4, n2 = EMB * EMB / 4;
    convert_f2h4<<<(n0 + 255) / 256, 256>>>((const float4*)query, n0, 0);
    convert_f2h4<<<(n1 + 255) / 256, 256>>>((const float4*)w_in,  n1, 1);
    convert_f2h4<<<(n2 + 255) / 256, 256>>>((const float4*)w_out, n2, 2);

    // QKV: M=4096, N=3072, K=1024
    gemm_h<0><<<dim3(3 * EMB / BN, MTOT / BM), 256>>>(b_in, nullptr);
    // Attention
    flash_h<<<dim3(SQ / 64, NB * NH), 128>>>();
    // Out proj: M=4096, N=1024, K=1024
    gemm_h<1><<<dim3(EMB / BN, MTOT / BM), 256>>>(b_out, out);
}

// round 7
// speedup vs baseline: 8.1137x; 1.0024x over previous
#include <cuda_runtime.h>
#include <cuda_fp16.h>
#include <math.h>

// Problem constants
#define SQ   2048
#define NB   2
#define EMB  1024
#define NH   16
#define HD   64
#define MTOT (SQ * NB)          // 4096
#define SCALE 0.125f

// ---------------- fp16 scratch (allocation-free: __device__ globals) -------
__device__ __half g_xh [(size_t)MTOT * EMB];        // query fp16, m-major
__device__ __half g_w1h[(size_t)3 * EMB * EMB];     // in_proj_weight fp16
__device__ __half g_w2h[(size_t)EMB * EMB];         // out_w fp16
__device__ __half g_qh [(size_t)NB * NH * SQ * HD]; // (b,h,s,d), pre-scaled
__device__ __half g_kh [(size_t)NB * NH * SQ * HD]; // (b,h,s,d)
__device__ __half g_vth[(size_t)NB * NH * HD * SQ]; // (b,h,d,s)  TRANSPOSED
__device__ __half g_ctxh[(size_t)NB * NH * SQ * HD];// (b,h,s,d)

// ---------------- helpers --------------------------------------------------
__device__ __forceinline__ unsigned smem_u32p(const void* p) {
    return (unsigned)__cvta_generic_to_shared(p);
}
__device__ __forceinline__ void cpa16(unsigned dst, const void* src) {
    asm volatile("cp.async.cg.shared.global [%0], [%1], 16;\n" :: "r"(dst), "l"(src));
}
__device__ __forceinline__ void cp_commit() { asm volatile("cp.async.commit_group;\n"); }
__device__ __forceinline__ void cp_wait0()  { asm volatile("cp.async.wait_group 0;\n" ::: "memory"); }
__device__ __forceinline__ void cp_wait1()  { asm volatile("cp.async.wait_group 1;\n" ::: "memory"); }

__device__ __forceinline__ void mma16816(float* c, const unsigned* a, const unsigned* b) {
    asm volatile(
        "mma.sync.aligned.m16n8k16.row.col.f32.f16.f16.f32 "
        "{%0,%1,%2,%3},{%4,%5,%6,%7},{%8,%9},{%0,%1,%2,%3};\n"
        : "+f"(c[0]), "+f"(c[1]), "+f"(c[2]), "+f"(c[3])
        : "r"(a[0]), "r"(a[1]), "r"(a[2]), "r"(a[3]), "r"(b[0]), "r"(b[1]));
}
__device__ __forceinline__ void ldsmx4(unsigned* r, const __half* p) {
    unsigned addr = smem_u32p(p);
    asm volatile("ldmatrix.sync.aligned.m8n8.x4.shared.b16 {%0,%1,%2,%3}, [%4];\n"
        : "=r"(r[0]), "=r"(r[1]), "=r"(r[2]), "=r"(r[3]) : "r"(addr));
}

// ---------------- fp32 -> fp16 convert (one fused launch) ------------------
#define N4_X  (MTOT * EMB / 4)          // 1048576
#define N4_W1 (3 * EMB * EMB / 4)       // 786432
#define N4_W2 (EMB * EMB / 4)           // 262144
#define N4_ALL (N4_X + N4_W1 + N4_W2)

__global__ void convert_all(const float4* __restrict__ x,
                            const float4* __restrict__ w1,
                            const float4* __restrict__ w2)
{
    int i = blockIdx.x * blockDim.x + threadIdx.x;
    const float4* src;
    __half2* dst;
    int j;
    if (i < N4_X)                  { src = x;  dst = (__half2*)g_xh;  j = i; }
    else if (i < N4_X + N4_W1)     { src = w1; dst = (__half2*)g_w1h; j = i - N4_X; }
    else if (i < N4_ALL)           { src = w2; dst = (__half2*)g_w2h; j = i - N4_X - N4_W1; }
    else return;
    float4 v = src[j];
    dst[2 * j]     = __floats2half2_rn(v.x, v.y);
    dst[2 * j + 1] = __floats2half2_rn(v.z, v.w);
}

// ---------------- GEMM: C[m,n] = sum_k A[m,k] * W[n,k] ---------------------
// 128x128x32 tile, 8 warps (4x2), warp tile 32x64, mma m16n8k16.
// 3-stage cp.async pipeline; swizzled smem rows (64B, chunk^((row>>1)&3)).
#define BM 128
#define BN 128
#define BK 32

template<int MODE>
__global__ __launch_bounds__(256, 2)
void gemm_h(const float* __restrict__ bias, float* __restrict__ outp)
{
    __shared__ __align__(16) __half As[3][BM * BK];   // 3 x 8 KB
    __shared__ __align__(16) __half Ws[3][BN * BK];   // 3 x 8 KB  (total 48 KB)

    const __half* A = (MODE == 0) ? g_xh  : g_ctxh;
    const __half* W = (MODE == 0) ? g_w1h : g_w2h;

    int tid  = threadIdx.x;
    int bm   = blockIdx.y, bn = blockIdx.x;
    int warp = tid >> 5, lane = tid & 31;
    int wm = warp & 3, wn = warp >> 2;

    float c[2][8][4];
    #pragma unroll
    for (int mt = 0; mt < 2; mt++)
        #pragma unroll
        for (int nt = 0; nt < 8; nt++)
            #pragma unroll
            for (int i = 0; i < 4; i++) c[mt][nt][i] = 0.f;

    auto stage = [&](int buf, int k0) {
        #pragma unroll
        for (int j = 0; j < 2; j++) {
            int i = tid + j * 256;          // 0..511
            int row = i >> 2, cc = i & 3;   // chunk = 8 halves = 16B
            const __half* src;
            if (MODE == 0) {
                src = A + (size_t)(bm * BM + row) * EMB + k0 + cc * 8;
            } else {
                int m = bm * BM + row;
                int s = m >> 1, b = m & 1;
                int kg = k0 + cc * 8;
                src = A + (((size_t)(b * NH + (kg >> 6)) * SQ + s) * HD + (kg & 63));
            }
            int pc = cc ^ ((row >> 1) & 3);
            cpa16(smem_u32p(&As[buf][row * BK + pc * 8]), src);
        }
        #pragma unroll
        for (int j = 0; j < 2; j++) {
            int i = tid + j * 256;
            int row = i >> 2, cc = i & 3;
            int pc = cc ^ ((row >> 1) & 3);
            cpa16(smem_u32p(&Ws[buf][row * BK + pc * 8]),
                  W + (size_t)(bn * BN + row) * EMB + k0 + cc * 8);
        }
        cp_commit();
    };

    const int NKT = EMB / BK;   // 32
    stage(0, 0);
    stage(1, BK);

    int rd = 0, wr = 2;
    for (int t = 0; t < NKT; t++) {
        if (t < NKT - 1) cp_wait1(); else cp_wait0();
        __syncthreads();
        if (t + 2 < NKT) stage(wr, (t + 2) * BK);

        #pragma unroll
        for (int ks = 0; ks < 2; ks++) {
            unsigned afr[2][4], bfr[8][2];
            int cc = 2 * ks + (lane >> 4);
            #pragma unroll
            for (int mt = 0; mt < 2; mt++) {
                int r = wm * 32 + mt * 16 + (lane & 15);
                int pc = cc ^ ((r >> 1) & 3);
                ldsmx4(afr[mt], &As[rd][r * BK + pc * 8]);
            }
            #pragma unroll
            for (int np = 0; np < 4; np++) {
                int n = wn * 64 + np * 16 + (lane & 15);
                int pc = cc ^ ((n >> 1) & 3);
                unsigned rr[4];
                ldsmx4(rr, &Ws[rd][n * BK + pc * 8]);
                bfr[2 * np][0]     = rr[0]; bfr[2 * np][1]     = rr[2];
                bfr[2 * np + 1][0] = rr[1]; bfr[2 * np + 1][1] = rr[3];
            }
            #pragma unroll
            for (int mt = 0; mt < 2; mt++)
                #pragma unroll
                for (int nt = 0; nt < 8; nt++)
                    mma16816(c[mt][nt], afr[mt], bfr[nt]);
        }
        rd = (rd == 2) ? 0 : rd + 1;
        wr = (wr == 2) ? 0 : wr + 1;
    }

    // epilogue
    int g = lane >> 2, tig = lane & 3;
    #pragma unroll
    for (int mt = 0; mt < 2; mt++) {
        #pragma unroll
        for (int nt = 0; nt < 8; nt++) {
            #pragma unroll
            for (int i = 0; i < 4; i++) {
                int row = bm * BM + wm * 32 + mt * 16 + g + ((i >= 2) ? 8 : 0);
                int col = bn * BN + wn * 64 + nt * 8 + 2 * tig + (i & 1);
                float val = c[mt][nt][i] + bias[col];
                if (MODE == 0) {
                    int sec = col >> 10;          // 0=q 1=k 2=v
                    int r = col & 1023;
                    int h = r >> 6, d = r & 63;
                    int s = row >> 1, b = row & 1;
                    if (sec == 0)
                        g_qh[((size_t)(b * NH + h) * SQ + s) * HD + d] = __float2half(val * SCALE);
                    else if (sec == 1)
                        g_kh[((size_t)(b * NH + h) * SQ + s) * HD + d] = __float2half(val);
                    else
                        g_vth[((size_t)(b * NH + h) * HD + d) * SQ + s] = __float2half(val);
                } else {
                    outp[(size_t)row * EMB + col] = val;
                }
            }
        }
    }
}

// ---------------- Flash attention, fp16 HMMA, online softmax ---------------
// CTA: 64 query rows of one (b,h); 4 warps x 16 rows. K/V tiles of 64,
// double-buffered cp.async, swizzled 128B rows, ldmatrix fragments.
__global__ __launch_bounds__(128, 4)
void flash_h()
{
    __shared__ __align__(16) __half Qs[64 * HD];       // 8 KB
    __shared__ __align__(16) __half Ks[2][64 * HD];    // 16 KB
    __shared__ __align__(16) __half Vt[2][64 * HD];    // 16 KB  [hd][key]

    int bh = blockIdx.y;
    int q0 = blockIdx.x * 64;
    int tid = threadIdx.x, warp = tid >> 5, lane = tid & 31;
    int g = lane >> 2, tig = lane & 3;

    const __half* qbase = g_qh + ((size_t)bh * SQ + q0) * HD;
    const __half* kbase = g_kh + (size_t)bh * SQ * HD;
    const __half* vbase = g_vth + (size_t)bh * HD * SQ;

    auto stageKV = [&](int buf, int kt) {
        #pragma unroll
        for (int j = 0; j < 4; j++) {
            int i = tid + j * 128;          // 0..511
            int r = i >> 3, cc = i & 7;     // 8 chunks of 16B per 128B row
            int pc = cc ^ (r & 7);
            cpa16(smem_u32p(&Ks[buf][r * HD + pc * 8]),
                  kbase + (size_t)(kt + r) * HD + cc * 8);
            cpa16(smem_u32p(&Vt[buf][r * HD + pc * 8]),
                  vbase + (size_t)r * SQ + kt + cc * 8);
        }
        cp_commit();
    };

    // stage Q + first K/V tile
    #pragma unroll
    for (int j = 0; j < 4; j++) {
        int i = tid + j * 128;
        int r = i >> 3, cc = i & 7;
        int pc = cc ^ (r & 7);
        cpa16(smem_u32p(&Qs[r * HD + pc * 8]), qbase + (size_t)r * HD + cc * 8);
    }
    stageKV(0, 0);
    cp_wait0();
    __syncthreads();

    // Q fragments: 4 k-steps of m16k16 per warp (ldmatrix)
    unsigned qf[4][4];
    #pragma unroll
    for (int ks = 0; ks < 4; ks++) {
        int r = warp * 16 + (lane & 15);
        int cc = 2 * ks + (lane >> 4);
        int pc = cc ^ (r & 7);
        ldsmx4(qf[ks], &Qs[r * HD + pc * 8]);
    }

    float o[8][4];
    #pragma unroll
    for (int nt = 0; nt < 8; nt++)
        #pragma unroll
        for (int i = 0; i < 4; i++) o[nt][i] = 0.f;
    float m0 = -1e30f, m1 = -1e30f, l0 = 0.f, l1 = 0.f;

    const int NT = SQ / 64;   // 32
    for (int it = 0; it < NT; it++) {
        if (it > 0) {
            cp_wait0();        // tile it arrived
            __syncthreads();   // all warps done reading buf^1 (tile it-1)
        }
        if (it + 1 < NT) stageKV((it + 1) & 1, (it + 1) * 64);
        int buf = it & 1;

        // S = Q K^T  (16 x 64 per warp)
        float s[8][4];
        #pragma unroll
        for (int nt = 0; nt < 8; nt++)
            #pragma unroll
            for (int i = 0; i < 4; i++) s[nt][i] = 0.f;
        #pragma unroll
        for (int ks = 0; ks < 4; ks++) {
            int cc = 2 * ks + (lane >> 4);
            #pragma unroll
            for (int np = 0; np < 4; np++) {
                int n = np * 16 + (lane & 15);
                int pc = cc ^ (n & 7);
                unsigned rr[4];
                ldsmx4(rr, &Ks[buf][n * HD + pc * 8]);
                unsigned bA[2] = {rr[0], rr[2]};
                unsigned bB[2] = {rr[1], rr[3]};
                mma16816(s[2 * np],     qf[ks], bA);
                mma16816(s[2 * np + 1], qf[ks], bB);
            }
        }

        // rowwise max (rows g -> m0, g+8 -> m1)
        float t0 = -1e30f, t1 = -1e30f;
        #pragma unroll
        for (int nt = 0; nt < 8; nt++) {
            t0 = fmaxf(t0, fmaxf(s[nt][0], s[nt][1]));
            t1 = fmaxf(t1, fmaxf(s[nt][2], s[nt][3]));
        }
        t0 = fmaxf(t0, __shfl_xor_sync(0xffffffffu, t0, 1));
        t0 = fmaxf(t0, __shfl_xor_sync(0xffffffffu, t0, 2));
        t1 = fmaxf(t1, __shfl_xor_sync(0xffffffffu, t1, 1));
        t1 = fmaxf(t1, __shfl_xor_sync(0xffffffffu, t1, 2));

        float nm0 = fmaxf(m0, t0), nm1 = fmaxf(m1, t1);
        float sc0 = __expf(m0 - nm0), sc1 = __expf(m1 - nm1);
        m0 = nm0; m1 = nm1;
        l0 *= sc0; l1 *= sc1;
        #pragma unroll
        for (int nt = 0; nt < 8; nt++) {
            o[nt][0] *= sc0; o[nt][1] *= sc0;
            o[nt][2] *= sc1; o[nt][3] *= sc1;
        }

        // P = exp(S - m); pack to fp16 A-fragments; accumulate l from ROUNDED P
        unsigned pf[4][4];
        float ps0 = 0.f, ps1 = 0.f;
        #pragma unroll
        for (int ks = 0; ks < 4; ks++) {
            int ta = 2 * ks, tb = 2 * ks + 1;
            __half2 h0 = __floats2half2_rn(__expf(s[ta][0] - m0), __expf(s[ta][1] - m0));
            __half2 h1 = __floats2half2_rn(__expf(s[ta][2] - m1), __expf(s[ta][3] - m1));
            __half2 h2 = __floats2half2_rn(__expf(s[tb][0] - m0), __expf(s[tb][1] - m0));
            __half2 h3 = __floats2half2_rn(__expf(s[tb][2] - m1), __expf(s[tb][3] - m1));
            pf[ks][0] = *(unsigned*)&h0;
            pf[ks][1] = *(unsigned*)&h1;
            pf[ks][2] = *(unsigned*)&h2;
            pf[ks][3] = *(unsigned*)&h3;
            float2 f;
            f = __half22float2(h0); ps0 += f.x + f.y;
            f = __half22float2(h2); ps0 += f.x + f.y;
            f = __half22float2(h1); ps1 += f.x + f.y;
            f = __half22float2(h3); ps1 += f.x + f.y;
        }
        ps0 += __shfl_xor_sync(0xffffffffu, ps0, 1);
        ps0 += __shfl_xor_sync(0xffffffffu, ps0, 2);
        ps1 += __shfl_xor_sync(0xffffffffu, ps1, 1);
        ps1 += __shfl_xor_sync(0xffffffffu, ps1, 2);
        l0 += ps0; l1 += ps1;

        // O += P V   (B fragments from transposed V tile via ldmatrix)
        #pragma unroll
        for (int ks = 0; ks < 4; ks++) {
            int cc = 2 * ks + (lane >> 4);      // key-chunk
            #pragma unroll
            for (int np = 0; np < 4; np++) {
                int r = np * 16 + (lane & 15);  // d-dim row
                int pc = cc ^ (r & 7);
                unsigned rr[4];
                ldsmx4(rr, &Vt[buf][r * HD + pc * 8]);
                unsigned bA[2] = {rr[0], rr[2]};
                unsigned bB[2] = {rr[1], rr[3]};
                mma16816(o[2 * np],     pf[ks], bA);
                mma16816(o[2 * np + 1], pf[ks], bB);
            }
        }
    }

    // normalize + write ctx (fp16)
    float inv0 = 1.f / l0, inv1 = 1.f / l1;
    int row0 = q0 + warp * 16 + g;
    __half* obase = g_ctxh + (size_t)bh * SQ * HD;
    #pragma unroll
    for (int nt = 0; nt < 8; nt++) {
        int colb = nt * 8 + 2 * tig;
        __half2 ha = __floats2half2_rn(o[nt][0] * inv0, o[nt][1] * inv0);
        __half2 hb = __floats2half2_rn(o[nt][2] * inv1, o[nt][3] * inv1);
        *(__half2*)&obase[(size_t)row0 * HD + colb] = ha;
        *(__half2*)&obase[(size_t)(row0 + 8) * HD + colb] = hb;
    }
}

// ---------------------------------------------------------------------------
extern "C" void kernel_launch(void* const* d_in, const int* in_sizes, int n_in,
                              void* d_out, int out_size)
{
    const float* query = (const float*)d_in[0];   // (S,B,E)
    const float* w_in  = (const float*)d_in[1];   // (3E,E)
    const float* b_in  = (const float*)d_in[2];   // (3E,)
    const float* w_out = (const float*)d_in[3];   // (E,E)
    const float* b_out = (const float*)d_in[4];   // (E,)
    float* out = (float*)d_out;                   // (S,B,E)

    convert_all<<<(N4_ALL + 255) / 256, 256>>>((const float4*)query,
                                               (const float4*)w_in,
                                               (const float4*)w_out);

    // QKV: M=4096, N=3072, K=1024
    gemm_h<0><<<dim3(3 * EMB / BN, MTOT / BM), 256>>>(b_in, nullptr);
    // Attention
    flash_h<<<dim3(SQ / 64, NB * NH), 128>>>();
    // Out proj: M=4096, N=1024, K=1024
    gemm_h<1><<<dim3(EMB / BN, MTOT / BM), 256>>>(b_out, out);
}

// round 9
// speedup vs baseline: 8.6930x; 1.0714x over previous
#include <cuda_runtime.h>
#include <cuda_fp16.h>
#include <math.h>

// Problem constants
#define SQ   2048
#define NB   2
#define EMB  1024
#define NH   16
#define HD   64
#define MTOT (SQ * NB)          // 4096
#define SCALE 0.125f
#define LOG2E 1.44269504088896f

// ---------------- fp16 scratch (allocation-free: __device__ globals) -------
__device__ __half g_xh [(size_t)MTOT * EMB];        // query fp16, m-major
__device__ __half g_w1h[(size_t)3 * EMB * EMB];     // in_proj_weight fp16
__device__ __half g_w2h[(size_t)EMB * EMB];         // out_w fp16
__device__ __half g_qh [(size_t)NB * NH * SQ * HD]; // (b,h,s,d), pre-scaled by SCALE*LOG2E
__device__ __half g_kh [(size_t)NB * NH * SQ * HD]; // (b,h,s,d)
__device__ __half g_vth[(size_t)NB * NH * HD * SQ]; // (b,h,d,s)  TRANSPOSED
__device__ __half g_ctxh[(size_t)NB * NH * SQ * HD];// (b,h,s,d)

// ---------------- helpers --------------------------------------------------
__device__ __forceinline__ unsigned smem_u32p(const void* p) {
    return (unsigned)__cvta_generic_to_shared(p);
}
__device__ __forceinline__ void cpa16(unsigned dst, const void* src) {
    asm volatile("cp.async.cg.shared.global [%0], [%1], 16;\n" :: "r"(dst), "l"(src));
}
__device__ __forceinline__ void cp_commit() { asm volatile("cp.async.commit_group;\n"); }
__device__ __forceinline__ void cp_wait0()  { asm volatile("cp.async.wait_group 0;\n" ::: "memory"); }

__device__ __forceinline__ void mma16816(float* c, const unsigned* a, const unsigned* b) {
    asm volatile(
        "mma.sync.aligned.m16n8k16.row.col.f32.f16.f16.f32 "
        "{%0,%1,%2,%3},{%4,%5,%6,%7},{%8,%9},{%0,%1,%2,%3};\n"
        : "+f"(c[0]), "+f"(c[1]), "+f"(c[2]), "+f"(c[3])
        : "r"(a[0]), "r"(a[1]), "r"(a[2]), "r"(a[3]), "r"(b[0]), "r"(b[1]));
}
__device__ __forceinline__ void ldsmx4(unsigned* r, const __half* p) {
    unsigned addr = smem_u32p(p);
    asm volatile("ldmatrix.sync.aligned.m8n8.x4.shared.b16 {%0,%1,%2,%3}, [%4];\n"
        : "=r"(r[0]), "=r"(r[1]), "=r"(r[2]), "=r"(r[3]) : "r"(addr));
}
__device__ __forceinline__ void ldsmx4a(unsigned* r, unsigned addr) {
    asm volatile("ldmatrix.sync.aligned.m8n8.x4.shared.b16 {%0,%1,%2,%3}, [%4];\n"
        : "=r"(r[0]), "=r"(r[1]), "=r"(r[2]), "=r"(r[3]) : "r"(addr));
}

// ---------------- fp32 -> fp16 convert (one fused launch) ------------------
#define N4_X  (MTOT * EMB / 4)
#define N4_W1 (3 * EMB * EMB / 4)
#define N4_W2 (EMB * EMB / 4)
#define N4_ALL (N4_X + N4_W1 + N4_W2)

__global__ void convert_all(const float4* __restrict__ x,
                            const float4* __restrict__ w1,
                            const float4* __restrict__ w2)
{
    int i = blockIdx.x * blockDim.x + threadIdx.x;
    const float4* src;
    __half2* dst;
    int j;
    if (i < N4_X)                  { src = x;  dst = (__half2*)g_xh;  j = i; }
    else if (i < N4_X + N4_W1)     { src = w1; dst = (__half2*)g_w1h; j = i - N4_X; }
    else if (i < N4_ALL)           { src = w2; dst = (__half2*)g_w2h; j = i - N4_X - N4_W1; }
    else return;
    float4 v = src[j];
    dst[2 * j]     = __floats2half2_rn(v.x, v.y);
    dst[2 * j + 1] = __floats2half2_rn(v.z, v.w);
}

// ---------------- GEMM: C[m,n] = sum_k A[m,k] * W[n,k] ---------------------
// 128x128x64 tile, 8 warps (4x2), warp tile 32x64, mma m16n8k16.
// 2-stage cp.async; 128B swizzled rows (chunk ^ (row&7)); ldmatrix frags.
#define BM 128
#define BN 128
#define BK 64
#define TILE_B (BM * BK * 2)              // 16 KB per operand tile
#define GSMEM (1024 + 4 * TILE_B)         // align slack + 2 stages x (A+W)

template<int MODE>
__global__ __launch_bounds__(256)
void gemm_h(const float* __restrict__ bias, float* __restrict__ outp)
{
    extern __shared__ char dsm[];
    unsigned base = (smem_u32p(dsm) + 1023u) & ~1023u;
    // As[buf] at base + buf*TILE_B ; Ws[buf] at base + 2*TILE_B + buf*TILE_B

    const __half* A = (MODE == 0) ? g_xh  : g_ctxh;
    const __half* W = (MODE == 0) ? g_w1h : g_w2h;

    int tid  = threadIdx.x;
    int bm   = blockIdx.y, bn = blockIdx.x;
    int warp = tid >> 5, lane = tid & 31;
    int wm = warp & 3, wn = warp >> 2;

    float c[2][8][4];
    #pragma unroll
    for (int mt = 0; mt < 2; mt++)
        #pragma unroll
        for (int nt = 0; nt < 8; nt++)
            #pragma unroll
            for (int i = 0; i < 4; i++) c[mt][nt][i] = 0.f;

    auto stage = [&](int t, int buf) {
        int k0 = t * BK;
        unsigned ab = base + buf * TILE_B;
        unsigned wb = base + 2 * TILE_B + buf * TILE_B;
        #pragma unroll
        for (int j = 0; j < 4; j++) {
            int i = tid + j * 256;           // 0..1023
            int r = i >> 3, cc = i & 7;      // row, 16B chunk
            unsigned soff = r * 128 + ((cc ^ (r & 7)) * 16);
            const __half* asrc;
            if (MODE == 0) {
                asrc = A + (size_t)(bm * BM + r) * EMB + k0 + cc * 8;
            } else {
                int m = bm * BM + r;
                int s = m >> 1, b = m & 1;
                int kg = k0 + cc * 8;
                asrc = A + (((size_t)(b * NH + (kg >> 6)) * SQ + s) * HD + (kg & 63));
            }
            cpa16(ab + soff, asrc);
            cpa16(wb + soff, W + (size_t)(bn * BN + r) * EMB + k0 + cc * 8);
        }
        cp_commit();
    };

    const int NKT = EMB / BK;   // 16
    stage(0, 0);
    for (int t = 0; t < NKT; t++) {
        cp_wait0();
        __syncthreads();
        if (t + 1 < NKT) stage(t + 1, (t + 1) & 1);
        int buf = t & 1;
        unsigned ab = base + buf * TILE_B;
        unsigned wb = base + 2 * TILE_B + buf * TILE_B;

        #pragma unroll
        for (int ks = 0; ks < 4; ks++) {
            unsigned afr[2][4], bfr[8][2];
            int cc = 2 * ks + (lane >> 4);
            #pragma unroll
            for (int mt = 0; mt < 2; mt++) {
                int r = wm * 32 + mt * 16 + (lane & 15);
                int pc = cc ^ (r & 7);
                ldsmx4a(afr[mt], ab + r * 128 + pc * 16);
            }
            #pragma unroll
            for (int np = 0; np < 4; np++) {
                int n = wn * 64 + np * 16 + (lane & 15);
                int pc = cc ^ (n & 7);
                unsigned rr[4];
                ldsmx4a(rr, wb + n * 128 + pc * 16);
                bfr[2 * np][0]     = rr[0]; bfr[2 * np][1]     = rr[2];
                bfr[2 * np + 1][0] = rr[1]; bfr[2 * np + 1][1] = rr[3];
            }
            #pragma unroll
            for (int mt = 0; mt < 2; mt++)
                #pragma unroll
                for (int nt = 0; nt < 8; nt++)
                    mma16816(c[mt][nt], afr[mt], bfr[nt]);
        }
    }

    // epilogue
    int g = lane >> 2, tig = lane & 3;
    #pragma unroll
    for (int mt = 0; mt < 2; mt++) {
        #pragma unroll
        for (int nt = 0; nt < 8; nt++) {
            #pragma unroll
            for (int i = 0; i < 4; i++) {
                int row = bm * BM + wm * 32 + mt * 16 + g + ((i >= 2) ? 8 : 0);
                int col = bn * BN + wn * 64 + nt * 8 + 2 * tig + (i & 1);
                float val = c[mt][nt][i] + bias[col];
                if (MODE == 0) {
                    int sec = col >> 10;          // 0=q 1=k 2=v
                    int r = col & 1023;
                    int h = r >> 6, d = r & 63;
                    int s = row >> 1, b = row & 1;
                    if (sec == 0)
                        g_qh[((size_t)(b * NH + h) * SQ + s) * HD + d] =
                            __float2half(val * (SCALE * LOG2E));
                    else if (sec == 1)
                        g_kh[((size_t)(b * NH + h) * SQ + s) * HD + d] = __float2half(val);
                    else
                        g_vth[((size_t)(b * NH + h) * HD + d) * SQ + s] = __float2half(val);
                } else {
                    outp[(size_t)row * EMB + col] = val;
                }
            }
        }
    }
}

// ---------------- Flash attention, fp16 HMMA, exp2-domain softmax ----------
// CTA: 64 query rows of one (b,h); 4 warps x 16 rows. K/V tiles of 64,
// double-buffered cp.async, swizzled 128B rows, ldmatrix fragments.
// Logits are pre-scaled by log2(e): p = exp2(s - m). Softmax invariant.
__global__ __launch_bounds__(128, 4)
void flash_h()
{
    __shared__ __align__(16) __half Qs[64 * HD];
    __shared__ __align__(16) __half Ks[2][64 * HD];
    __shared__ __align__(16) __half Vt[2][64 * HD];

    int bh = blockIdx.y;
    int q0 = blockIdx.x * 64;
    int tid = threadIdx.x, warp = tid >> 5, lane = tid & 31;
    int g = lane >> 2, tig = lane & 3;

    const __half* qbase = g_qh + ((size_t)bh * SQ + q0) * HD;
    const __half* kbase = g_kh + (size_t)bh * SQ * HD;
    const __half* vbase = g_vth + (size_t)bh * HD * SQ;

    auto stageKV = [&](int buf, int kt) {
        #pragma unroll
        for (int j = 0; j < 4; j++) {
            int i = tid + j * 128;
            int r = i >> 3, cc = i & 7;
            int pc = cc ^ (r & 7);
            cpa16(smem_u32p(&Ks[buf][r * HD + pc * 8]),
                  kbase + (size_t)(kt + r) * HD + cc * 8);
            cpa16(smem_u32p(&Vt[buf][r * HD + pc * 8]),
                  vbase + (size_t)r * SQ + kt + cc * 8);
        }
        cp_commit();
    };

    #pragma unroll
    for (int j = 0; j < 4; j++) {
        int i = tid + j * 128;
        int r = i >> 3, cc = i & 7;
        int pc = cc ^ (r & 7);
        cpa16(smem_u32p(&Qs[r * HD + pc * 8]), qbase + (size_t)r * HD + cc * 8);
    }
    stageKV(0, 0);
    cp_wait0();
    __syncthreads();

    unsigned qf[4][4];
    #pragma unroll
    for (int ks = 0; ks < 4; ks++) {
        int r = warp * 16 + (lane & 15);
        int cc = 2 * ks + (lane >> 4);
        int pc = cc ^ (r & 7);
        ldsmx4(qf[ks], &Qs[r * HD + pc * 8]);
    }

    float o[8][4];
    #pragma unroll
    for (int nt = 0; nt < 8; nt++)
        #pragma unroll
        for (int i = 0; i < 4; i++) o[nt][i] = 0.f;
    float m0 = -1e30f, m1 = -1e30f, l0 = 0.f, l1 = 0.f;

    const int NT = SQ / 64;
    for (int it = 0; it < NT; it++) {
        if (it > 0) {
            cp_wait0();
            __syncthreads();
        }
        if (it + 1 < NT) stageKV((it + 1) & 1, (it + 1) * 64);
        int buf = it & 1;

        float s[8][4];
        #pragma unroll
        for (int nt = 0; nt < 8; nt++)
            #pragma unroll
            for (int i = 0; i < 4; i++) s[nt][i] = 0.f;
        #pragma unroll
        for (int ks = 0; ks < 4; ks++) {
            int cc = 2 * ks + (lane >> 4);
            #pragma unroll
            for (int np = 0; np < 4; np++) {
                int n = np * 16 + (lane & 15);
                int pc = cc ^ (n & 7);
                unsigned rr[4];
                ldsmx4(rr, &Ks[buf][n * HD + pc * 8]);
                unsigned bA[2] = {rr[0], rr[2]};
                unsigned bB[2] = {rr[1], rr[3]};
                mma16816(s[2 * np],     qf[ks], bA);
                mma16816(s[2 * np + 1], qf[ks], bB);
            }
        }

        float t0 = -1e30f, t1 = -1e30f;
        #pragma unroll
        for (int nt = 0; nt < 8; nt++) {
            t0 = fmaxf(t0, fmaxf(s[nt][0], s[nt][1]));
            t1 = fmaxf(t1, fmaxf(s[nt][2], s[nt][3]));
        }
        t0 = fmaxf(t0, __shfl_xor_sync(0xffffffffu, t0, 1));
        t0 = fmaxf(t0, __shfl_xor_sync(0xffffffffu, t0, 2));
        t1 = fmaxf(t1, __shfl_xor_sync(0xffffffffu, t1, 1));
        t1 = fmaxf(t1, __shfl_xor_sync(0xffffffffu, t1, 2));

        float nm0 = fmaxf(m0, t0), nm1 = fmaxf(m1, t1);
        float sc0 = exp2f(m0 - nm0), sc1 = exp2f(m1 - nm1);
        m0 = nm0; m1 = nm1;
        l0 *= sc0; l1 *= sc1;
        #pragma unroll
        for (int nt = 0; nt < 8; nt++) {
            o[nt][0] *= sc0; o[nt][1] *= sc0;
            o[nt][2] *= sc1; o[nt][3] *= sc1;
        }

        unsigned pf[4][4];
        float ps0 = 0.f, ps1 = 0.f;
        #pragma unroll
        for (int ks = 0; ks < 4; ks++) {
            int ta = 2 * ks, tb = 2 * ks + 1;
            __half2 h0 = __floats2half2_rn(exp2f(s[ta][0] - m0), exp2f(s[ta][1] - m0));
            __half2 h1 = __floats2half2_rn(exp2f(s[ta][2] - m1), exp2f(s[ta][3] - m1));
            __half2 h2 = __floats2half2_rn(exp2f(s[tb][0] - m0), exp2f(s[tb][1] - m0));
            __half2 h3 = __floats2half2_rn(exp2f(s[tb][2] - m1), exp2f(s[tb][3] - m1));
            pf[ks][0] = *(unsigned*)&h0;
            pf[ks][1] = *(unsigned*)&h1;
            pf[ks][2] = *(unsigned*)&h2;
            pf[ks][3] = *(unsigned*)&h3;
            float2 f;
            f = __half22float2(h0); ps0 += f.x + f.y;
            f = __half22float2(h2); ps0 += f.x + f.y;
            f = __half22float2(h1); ps1 += f.x + f.y;
            f = __half22float2(h3); ps1 += f.x + f.y;
        }
        ps0 += __shfl_xor_sync(0xffffffffu, ps0, 1);
        ps0 += __shfl_xor_sync(0xffffffffu, ps0, 2);
        ps1 += __shfl_xor_sync(0xffffffffu, ps1, 1);
        ps1 += __shfl_xor_sync(0xffffffffu, ps1, 2);
        l0 += ps0; l1 += ps1;

        #pragma unroll
        for (int ks = 0; ks < 4; ks++) {
            int cc = 2 * ks + (lane >> 4);
            #pragma unroll
            for (int np = 0; np < 4; np++) {
                int r = np * 16 + (lane & 15);
                int pc = cc ^ (r & 7);
                unsigned rr[4];
                ldsmx4(rr, &Vt[buf][r * HD + pc * 8]);
                unsigned bA[2] = {rr[0], rr[2]};
                unsigned bB[2] = {rr[1], rr[3]};
                mma16816(o[2 * np],     pf[ks], bA);
                mma16816(o[2 * np + 1], pf[ks], bB);
            }
        }
    }

    float inv0 = 1.f / l0, inv1 = 1.f / l1;
    int row0 = q0 + warp * 16 + g;
    __half* obase = g_ctxh + (size_t)bh * SQ * HD;
    #pragma unroll
    for (int nt = 0; nt < 8; nt++) {
        int colb = nt * 8 + 2 * tig;
        __half2 ha = __floats2half2_rn(o[nt][0] * inv0, o[nt][1] * inv0);
        __half2 hb = __floats2half2_rn(o[nt][2] * inv1, o[nt][3] * inv1);
        *(__half2*)&obase[(size_t)row0 * HD + colb] = ha;
        *(__half2*)&obase[(size_t)(row0 + 8) * HD + colb] = hb;
    }
}

// ---------------------------------------------------------------------------
extern "C" void kernel_launch(void* const* d_in, const int* in_sizes, int n_in,
                              void* d_out, int out_size)
{
    const float* query = (const float*)d_in[0];   // (S,B,E)
    const float* w_in  = (const float*)d_in[1];   // (3E,E)
    const float* b_in  = (const float*)d_in[2];   // (3E,)
    const float* w_out = (const float*)d_in[3];   // (E,E)
    const float* b_out = (const float*)d_in[4];   // (E,)
    float* out = (float*)d_out;                   // (S,B,E)

    static int attr_done = 0;
    if (!attr_done) {
        cudaFuncSetAttribute(gemm_h<0>, cudaFuncAttributeMaxDynamicSharedMemorySize, GSMEM);
        cudaFuncSetAttribute(gemm_h<1>, cudaFuncAttributeMaxDynamicSharedMemorySize, GSMEM);
        attr_done = 1;
    }

    convert_all<<<(N4_ALL + 255) / 256, 256>>>((const float4*)query,
                                               (const float4*)w_in,
                                               (const float4*)w_out);

    // QKV: M=4096, N=3072, K=1024
    gemm_h<0><<<dim3(3 * EMB / BN, MTOT / BM), 256, GSMEM>>>(b_in, nullptr);
    // Attention
    flash_h<<<dim3(SQ / 64, NB * NH), 128>>>();
    // Out proj: M=4096, N=1024, K=1024
    gemm_h<1><<<dim3(EMB / BN, MTOT / BM), 256, GSMEM>>>(b_out, out);
}

// round 10
// speedup vs baseline: 9.0898x; 1.0456x over previous
#include <cuda_runtime.h>
#include <cuda_fp16.h>
#include <math.h>

// Problem constants
#define SQ   2048
#define NB   2
#define EMB  1024
#define NH   16
#define HD   64
#define MTOT (SQ * NB)          // 4096
#define SCALE 0.125f
#define LOG2E 1.44269504088896f

// ---------------- fp16 scratch (allocation-free: __device__ globals) -------
__device__ __half g_xh [(size_t)MTOT * EMB];        // query fp16, m-major
__device__ __half g_w1h[(size_t)3 * EMB * EMB];     // in_proj_weight fp16
__device__ __half g_w2h[(size_t)EMB * EMB];         // out_w fp16
__device__ __half g_qh [(size_t)NB * NH * SQ * HD]; // (b,h,s,d), pre-scaled by SCALE*LOG2E
__device__ __half g_kh [(size_t)NB * NH * SQ * HD]; // (b,h,s,d)
__device__ __half g_vth[(size_t)NB * NH * HD * SQ]; // (b,h,d,s)  TRANSPOSED
__device__ __half g_ctxh[(size_t)NB * NH * SQ * HD];// (b,h,s,d)

// ---------------- helpers --------------------------------------------------
__device__ __forceinline__ unsigned smem_u32p(const void* p) {
    return (unsigned)__cvta_generic_to_shared(p);
}
__device__ __forceinline__ void cpa16(unsigned dst, const void* src) {
    asm volatile("cp.async.cg.shared.global [%0], [%1], 16;\n" :: "r"(dst), "l"(src));
}
__device__ __forceinline__ void cp_commit() { asm volatile("cp.async.commit_group;\n"); }
__device__ __forceinline__ void cp_wait0()  { asm volatile("cp.async.wait_group 0;\n" ::: "memory"); }

__device__ __forceinline__ void mma16816(float* c, const unsigned* a, const unsigned* b) {
    asm volatile(
        "mma.sync.aligned.m16n8k16.row.col.f32.f16.f16.f32 "
        "{%0,%1,%2,%3},{%4,%5,%6,%7},{%8,%9},{%0,%1,%2,%3};\n"
        : "+f"(c[0]), "+f"(c[1]), "+f"(c[2]), "+f"(c[3])
        : "r"(a[0]), "r"(a[1]), "r"(a[2]), "r"(a[3]), "r"(b[0]), "r"(b[1]));
}
__device__ __forceinline__ void ldsmx4(unsigned* r, const __half* p) {
    unsigned addr = smem_u32p(p);
    asm volatile("ldmatrix.sync.aligned.m8n8.x4.shared.b16 {%0,%1,%2,%3}, [%4];\n"
        : "=r"(r[0]), "=r"(r[1]), "=r"(r[2]), "=r"(r[3]) : "r"(addr));
}
__device__ __forceinline__ void ldsmx4a(unsigned* r, unsigned addr) {
    asm volatile("ldmatrix.sync.aligned.m8n8.x4.shared.b16 {%0,%1,%2,%3}, [%4];\n"
        : "=r"(r[0]), "=r"(r[1]), "=r"(r[2]), "=r"(r[3]) : "r"(addr));
}

// ---------------- fp32 -> fp16 convert (one fused launch) ------------------
#define N4_X  (MTOT * EMB / 4)
#define N4_W1 (3 * EMB * EMB / 4)
#define N4_W2 (EMB * EMB / 4)
#define N4_ALL (N4_X + N4_W1 + N4_W2)

__global__ void convert_all(const float4* __restrict__ x,
                            const float4* __restrict__ w1,
                            const float4* __restrict__ w2)
{
    int i = blockIdx.x * blockDim.x + threadIdx.x;
    const float4* src;
    __half2* dst;
    int j;
    if (i < N4_X)                  { src = x;  dst = (__half2*)g_xh;  j = i; }
    else if (i < N4_X + N4_W1)     { src = w1; dst = (__half2*)g_w1h; j = i - N4_X; }
    else if (i < N4_ALL)           { src = w2; dst = (__half2*)g_w2h; j = i - N4_X - N4_W1; }
    else return;
    float4 v = src[j];
    dst[2 * j]     = __floats2half2_rn(v.x, v.y);
    dst[2 * j + 1] = __floats2half2_rn(v.z, v.w);
}

// ---------------- GEMM: C[m,n] = sum_k A[m,k] * W[n,k] ---------------------
// 128x128x64 tile, 8 warps (4x2), warp tile 32x64, mma m16n8k16.
// 2-stage cp.async; 128B swizzled rows (chunk ^ (row&7)); ldmatrix frags.
// Epilogues vectorized: q/k half2, out float2, V via smem transpose.
#define BM 128
#define BN 128
#define BK 64
#define TILE_B (BM * BK * 2)              // 16 KB per operand tile
#define GSMEM (1024 + 4 * TILE_B)         // align slack + 2 stages x (A+W)
#define VCT 130                           // V-transpose smem col stride (halves)

template<int MODE>
__global__ __launch_bounds__(256)
void gemm_h(const float* __restrict__ bias, float* __restrict__ outp)
{
    extern __shared__ char dsm[];
    unsigned base = (smem_u32p(dsm) + 1023u) & ~1023u;

    const __half* A = (MODE == 0) ? g_xh  : g_ctxh;
    const __half* W = (MODE == 0) ? g_w1h : g_w2h;

    int tid  = threadIdx.x;
    int bm   = blockIdx.y, bn = blockIdx.x;
    int warp = tid >> 5, lane = tid & 31;
    int wm = warp & 3, wn = warp >> 2;

    float c[2][8][4];
    #pragma unroll
    for (int mt = 0; mt < 2; mt++)
        #pragma unroll
        for (int nt = 0; nt < 8; nt++)
            #pragma unroll
            for (int i = 0; i < 4; i++) c[mt][nt][i] = 0.f;

    auto stage = [&](int t, int buf) {
        int k0 = t * BK;
        unsigned ab = base + buf * TILE_B;
        unsigned wb = base + 2 * TILE_B + buf * TILE_B;
        #pragma unroll
        for (int j = 0; j < 4; j++) {
            int i = tid + j * 256;           // 0..1023
            int r = i >> 3, cc = i & 7;      // row, 16B chunk
            unsigned soff = r * 128 + ((cc ^ (r & 7)) * 16);
            const __half* asrc;
            if (MODE == 0) {
                asrc = A + (size_t)(bm * BM + r) * EMB + k0 + cc * 8;
            } else {
                int m = bm * BM + r;
                int s = m >> 1, b = m & 1;
                int kg = k0 + cc * 8;
                asrc = A + (((size_t)(b * NH + (kg >> 6)) * SQ + s) * HD + (kg & 63));
            }
            cpa16(ab + soff, asrc);
            cpa16(wb + soff, W + (size_t)(bn * BN + r) * EMB + k0 + cc * 8);
        }
        cp_commit();
    };

    const int NKT = EMB / BK;   // 16
    stage(0, 0);
    for (int t = 0; t < NKT; t++) {
        cp_wait0();
        __syncthreads();
        if (t + 1 < NKT) stage(t + 1, (t + 1) & 1);
        int buf = t & 1;
        unsigned ab = base + buf * TILE_B;
        unsigned wb = base + 2 * TILE_B + buf * TILE_B;

        #pragma unroll
        for (int ks = 0; ks < 4; ks++) {
            unsigned afr[2][4], bfr[8][2];
            int cc = 2 * ks + (lane >> 4);
            #pragma unroll
            for (int mt = 0; mt < 2; mt++) {
                int r = wm * 32 + mt * 16 + (lane & 15);
                int pc = cc ^ (r & 7);
                ldsmx4a(afr[mt], ab + r * 128 + pc * 16);
            }
            #pragma unroll
            for (int np = 0; np < 4; np++) {
                int n = wn * 64 + np * 16 + (lane & 15);
                int pc = cc ^ (n & 7);
                unsigned rr[4];
                ldsmx4a(rr, wb + n * 128 + pc * 16);
                bfr[2 * np][0]     = rr[0]; bfr[2 * np][1]     = rr[2];
                bfr[2 * np + 1][0] = rr[1]; bfr[2 * np + 1][1] = rr[3];
            }
            #pragma unroll
            for (int mt = 0; mt < 2; mt++)
                #pragma unroll
                for (int nt = 0; nt < 8; nt++)
                    mma16816(c[mt][nt], afr[mt], bfr[nt]);
        }
    }

    // ---------------- epilogue ----------------
    int g = lane >> 2, tig = lane & 3;
    int sec = (MODE == 0) ? ((bn * BN) >> 10) : 1;   // uniform per CTA (128 | 1024)

    if (MODE == 0 && sec == 2) {
        // V block: transpose through smem, then coalesced stores along s.
        __syncthreads();                      // mainloop smem reads done
        __half* ct = (__half*)dsm;            // 128 cols x VCT halves = 33,280 B
        #pragma unroll
        for (int mt = 0; mt < 2; mt++) {
            #pragma unroll
            for (int nt = 0; nt < 8; nt++) {
                #pragma unroll
                for (int i = 0; i < 4; i++) {
                    int rowL = wm * 32 + mt * 16 + g + ((i >= 2) ? 8 : 0);
                    int colL = wn * 64 + nt * 8 + 2 * tig + (i & 1);
                    int col = bn * BN + colL;
                    ct[colL * VCT + rowL] = __float2half(c[mt][nt][i] + __ldg(&bias[col]));
                }
            }
        }
        __syncthreads();
        // thread -> (col, s-half). 32 contiguous s per store target, both b.
        int colL = tid >> 1, sh = tid & 1;
        int col = bn * BN + colL;
        int r = col & 1023;
        int h = r >> 6, d = r & 63;
        const unsigned* src = (const unsigned*)(ct + colL * VCT);  // 4B-aligned (VCT even)
        unsigned w0[16], w1[16];
        #pragma unroll
        for (int tt = 0; tt < 16; tt++) {
            unsigned ua = src[sh * 32 + 2 * tt];       // halves: (b0,b1) for s=...
            unsigned ub = src[sh * 32 + 2 * tt + 1];
            w0[tt] = __byte_perm(ua, ub, 0x5410);      // b=0 halves packed
            w1[tt] = __byte_perm(ua, ub, 0x7632);      // b=1 halves packed
        }
        int s0 = bm * 64 + sh * 32;
        __half* d0 = g_vth + ((size_t)(0 * NH + h) * HD + d) * SQ + s0;
        __half* d1 = g_vth + ((size_t)(1 * NH + h) * HD + d) * SQ + s0;
        #pragma unroll
        for (int q4 = 0; q4 < 4; q4++) {
            *(uint4*)(d0 + q4 * 8) = *(uint4*)&w0[q4 * 4];
            *(uint4*)(d1 + q4 * 8) = *(uint4*)&w1[q4 * 4];
        }
    } else {
        #pragma unroll
        for (int mt = 0; mt < 2; mt++) {
            #pragma unroll
            for (int nt = 0; nt < 8; nt++) {
                int colL = wn * 64 + nt * 8 + 2 * tig;
                int col = bn * BN + colL;
                float b0 = __ldg(&bias[col]), b1 = __ldg(&bias[col + 1]);
                #pragma unroll
                for (int half = 0; half < 2; half++) {   // i pair (0,1) / (2,3)
                    int row = bm * BM + wm * 32 + mt * 16 + g + half * 8;
                    float v0 = c[mt][nt][2 * half]     + b0;
                    float v1 = c[mt][nt][2 * half + 1] + b1;
                    if (MODE == 0) {
                        int rr = col & 1023;
                        int h = rr >> 6, d = rr & 63;    // d even
                        int s = row >> 1, b = row & 1;
                        if (sec == 0) {
                            __half2 h2 = __floats2half2_rn(v0 * (SCALE * LOG2E),
                                                           v1 * (SCALE * LOG2E));
                            *(__half2*)&g_qh[((size_t)(b * NH + h) * SQ + s) * HD + d] = h2;
                        } else {
                            __half2 h2 = __floats2half2_rn(v0, v1);
                            *(__half2*)&g_kh[((size_t)(b * NH + h) * SQ + s) * HD + d] = h2;
                        }
                    } else {
                        float2 f2 = make_float2(v0, v1);
                        *(float2*)&outp[(size_t)row * EMB + col] = f2;
                    }
                }
            }
        }
    }
}

// ---------------- Flash attention, fp16 HMMA, exp2-domain softmax ----------
// (unchanged from R9)
__global__ __launch_bounds__(128, 4)
void flash_h()
{
    __shared__ __align__(16) __half Qs[64 * HD];
    __shared__ __align__(16) __half Ks[2][64 * HD];
    __shared__ __align__(16) __half Vt[2][64 * HD];

    int bh = blockIdx.y;
    int q0 = blockIdx.x * 64;
    int tid = threadIdx.x, warp = tid >> 5, lane = tid & 31;
    int g = lane >> 2, tig = lane & 3;

    const __half* qbase = g_qh + ((size_t)bh * SQ + q0) * HD;
    const __half* kbase = g_kh + (size_t)bh * SQ * HD;
    const __half* vbase = g_vth + (size_t)bh * HD * SQ;

    auto stageKV = [&](int buf, int kt) {
        #pragma unroll
        for (int j = 0; j < 4; j++) {
            int i = tid + j * 128;
            int r = i >> 3, cc = i & 7;
            int pc = cc ^ (r & 7);
            cpa16(smem_u32p(&Ks[buf][r * HD + pc * 8]),
                  kbase + (size_t)(kt + r) * HD + cc * 8);
            cpa16(smem_u32p(&Vt[buf][r * HD + pc * 8]),
                  vbase + (size_t)r * SQ + kt + cc * 8);
        }
        cp_commit();
    };

    #pragma unroll
    for (int j = 0; j < 4; j++) {
        int i = tid + j * 128;
        int r = i >> 3, cc = i & 7;
        int pc = cc ^ (r & 7);
        cpa16(smem_u32p(&Qs[r * HD + pc * 8]), qbase + (size_t)r * HD + cc * 8);
    }
    stageKV(0, 0);
    cp_wait0();
    __syncthreads();

    unsigned qf[4][4];
    #pragma unroll
    for (int ks = 0; ks < 4; ks++) {
        int r = warp * 16 + (lane & 15);
        int cc = 2 * ks + (lane >> 4);
        int pc = cc ^ (r & 7);
        ldsmx4(qf[ks], &Qs[r * HD + pc * 8]);
    }

    float o[8][4];
    #pragma unroll
    for (int nt = 0; nt < 8; nt++)
        #pragma unroll
        for (int i = 0; i < 4; i++) o[nt][i] = 0.f;
    float m0 = -1e30f, m1 = -1e30f, l0 = 0.f, l1 = 0.f;

    const int NT = SQ / 64;
    for (int it = 0; it < NT; it++) {
        if (it > 0) {
            cp_wait0();
            __syncthreads();
        }
        if (it + 1 < NT) stageKV((it + 1) & 1, (it + 1) * 64);
        int buf = it & 1;

        float s[8][4];
        #pragma unroll
        for (int nt = 0; nt < 8; nt++)
            #pragma unroll
            for (int i = 0; i < 4; i++) s[nt][i] = 0.f;
        #pragma unroll
        for (int ks = 0; ks < 4; ks++) {
            int cc = 2 * ks + (lane >> 4);
            #pragma unroll
            for (int np = 0; np < 4; np++) {
                int n = np * 16 + (lane & 15);
                int pc = cc ^ (n & 7);
                unsigned rr[4];
                ldsmx4(rr, &Ks[buf][n * HD + pc * 8]);
                unsigned bA[2] = {rr[0], rr[2]};
                unsigned bB[2] = {rr[1], rr[3]};
                mma16816(s[2 * np],     qf[ks], bA);
                mma16816(s[2 * np + 1], qf[ks], bB);
            }
        }

        float t0 = -1e30f, t1 = -1e30f;
        #pragma unroll
        for (int nt = 0; nt < 8; nt++) {
            t0 = fmaxf(t0, fmaxf(s[nt][0], s[nt][1]));
            t1 = fmaxf(t1, fmaxf(s[nt][2], s[nt][3]));
        }
        t0 = fmaxf(t0, __shfl_xor_sync(0xffffffffu, t0, 1));
        t0 = fmaxf(t0, __shfl_xor_sync(0xffffffffu, t0, 2));
        t1 = fmaxf(t1, __shfl_xor_sync(0xffffffffu, t1, 1));
        t1 = fmaxf(t1, __shfl_xor_sync(0xffffffffu, t1, 2));

        float nm0 = fmaxf(m0, t0), nm1 = fmaxf(m1, t1);
        float sc0 = exp2f(m0 - nm0), sc1 = exp2f(m1 - nm1);
        m0 = nm0; m1 = nm1;
        l0 *= sc0; l1 *= sc1;
        #pragma unroll
        for (int nt = 0; nt < 8; nt++) {
            o[nt][0] *= sc0; o[nt][1] *= sc0;
            o[nt][2] *= sc1; o[nt][3] *= sc1;
        }

        unsigned pf[4][4];
        float ps0 = 0.f, ps1 = 0.f;
        #pragma unroll
        for (int ks = 0; ks < 4; ks++) {
            int ta = 2 * ks, tb = 2 * ks + 1;
            __half2 h0 = __floats2half2_rn(exp2f(s[ta][0] - m0), exp2f(s[ta][1] - m0));
            __half2 h1 = __floats2half2_rn(exp2f(s[ta][2] - m1), exp2f(s[ta][3] - m1));
            __half2 h2 = __floats2half2_rn(exp2f(s[tb][0] - m0), exp2f(s[tb][1] - m0));
            __half2 h3 = __floats2half2_rn(exp2f(s[tb][2] - m1), exp2f(s[tb][3] - m1));
            pf[ks][0] = *(unsigned*)&h0;
            pf[ks][1] = *(unsigned*)&h1;
            pf[ks][2] = *(unsigned*)&h2;
            pf[ks][3] = *(unsigned*)&h3;
            float2 f;
            f = __half22float2(h0); ps0 += f.x + f.y;
            f = __half22float2(h2); ps0 += f.x + f.y;
            f = __half22float2(h1); ps1 += f.x + f.y;
            f = __half22float2(h3); ps1 += f.x + f.y;
        }
        ps0 += __shfl_xor_sync(0xffffffffu, ps0, 1);
        ps0 += __shfl_xor_sync(0xffffffffu, ps0, 2);
        ps1 += __shfl_xor_sync(0xffffffffu, ps1, 1);
        ps1 += __shfl_xor_sync(0xffffffffu, ps1, 2);
        l0 += ps0; l1 += ps1;

        #pragma unroll
        for (int ks = 0; ks < 4; ks++) {
            int cc = 2 * ks + (lane >> 4);
            #pragma unroll
            for (int np = 0; np < 4; np++) {
                int r = np * 16 + (lane & 15);
                int pc = cc ^ (r & 7);
                unsigned rr[4];
                ldsmx4(rr, &Vt[buf][r * HD + pc * 8]);
                unsigned bA[2] = {rr[0], rr[2]};
                unsigned bB[2] = {rr[1], rr[3]};
                mma16816(o[2 * np],     pf[ks], bA);
                mma16816(o[2 * np + 1], pf[ks], bB);
            }
        }
    }

    float inv0 = 1.f / l0, inv1 = 1.f / l1;
    int row0 = q0 + warp * 16 + g;
    __half* obase = g_ctxh + (size_t)bh * SQ * HD;
    #pragma unroll
    for (int nt = 0; nt < 8; nt++) {
        int colb = nt * 8 + 2 * tig;
        __half2 ha = __floats2half2_rn(o[nt][0] * inv0, o[nt][1] * inv0);
        __half2 hb = __floats2half2_rn(o[nt][2] * inv1, o[nt][3] * inv1);
        *(__half2*)&obase[(size_t)row0 * HD + colb] = ha;
        *(__half2*)&obase[(size_t)(row0 + 8) * HD + colb] = hb;
    }
}

// ---------------------------------------------------------------------------
extern "C" void kernel_launch(void* const* d_in, const int* in_sizes, int n_in,
                              void* d_out, int out_size)
{
    const float* query = (const float*)d_in[0];   // (S,B,E)
    const float* w_in  = (const float*)d_in[1];   // (3E,E)
    const float* b_in  = (const float*)d_in[2];   // (3E,)
    const float* w_out = (const float*)d_in[3];   // (E,E)
    const float* b_out = (const float*)d_in[4];   // (E,)
    float* out = (float*)d_out;                   // (S,B,E)

    static int attr_done = 0;
    if (!attr_done) {
        cudaFuncSetAttribute(gemm_h<0>, cudaFuncAttributeMaxDynamicSharedMemorySize, GSMEM);
        cudaFuncSetAttribute(gemm_h<1>, cudaFuncAttributeMaxDynamicSharedMemorySize, GSMEM);
        attr_done = 1;
    }

    convert_all<<<(N4_ALL + 255) / 256, 256>>>((const float4*)query,
                                               (const float4*)w_in,
                                               (const float4*)w_out);

    // QKV: M=4096, N=3072, K=1024
    gemm_h<0><<<dim3(3 * EMB / BN, MTOT / BM), 256, GSMEM>>>(b_in, nullptr);
    // Attention
    flash_h<<<dim3(SQ / 64, NB * NH), 128>>>();
    // Out proj: M=4096, N=1024, K=1024
    gemm_h<1><<<dim3(EMB / BN, MTOT / BM), 256, GSMEM>>>(b_out, out);
}